// round 1
// baseline (speedup 1.0000x reference)
#include <cuda_runtime.h>
#include <cstdint>

// ---------------- problem constants ----------------
#define BB 64
#define TT 256
#define BT (BB*TT)          // 16384 windows
#define WW 20
#define NP 6
#define NT 12
#define CH 32
#define FRAG 8
#define PROJ 64
#define GATES 256           // 4*PROJ

// ---------------- scratch (static device memory; no allocs allowed) -------
__device__ float g_enc[BT * 64];      // [win][0:32]=pf, [32:64]=tf   (4 MB)
__device__ float g_feat[BT * PROJ];   // projected features           (4 MB)
__device__ float g_xg[BT * GATES];    // precomputed input gates      (16 MB)
__device__ float g_lstm[BT * PROJ];   // lstm hidden outputs          (4 MB)

__device__ __forceinline__ float sigf(float x) {
    return 1.0f / (1.0f + __expf(-x));
}

// =====================================================================
// Kernel 1: conv encoders (pressure + torque), warp-per-window.
// lane = output channel. Weights in SMEM transposed to [row][c] so each
// lane reads its own channel conflict-free; activations read via warp
// broadcast (all lanes same address).
// =====================================================================
__global__ __launch_bounds__(128) void enc_kernel(
    const float* __restrict__ pressure, const float* __restrict__ torque,
    const float* __restrict__ pw1, const float* __restrict__ pb1,
    const float* __restrict__ pw2, const float* __restrict__ pb2,
    const float* __restrict__ tw1, const float* __restrict__ tb1,
    const float* __restrict__ tw2, const float* __restrict__ tb2)
{
    __shared__ float pw1s[18 * 32];   // [(i*3+k)][c]
    __shared__ float pw2s[96 * 32];
    __shared__ float tw1s[36 * 32];
    __shared__ float tw2s[96 * 32];
    __shared__ float xs[4][240];      // raw window (max torque: 20*12)
    __shared__ float h1s[4][18 * 32]; // conv1 output, [l][c]

    int tid = threadIdx.x;
    // weight staging, transposed: w[c][r] -> s[r*32+c]
    for (int idx = tid; idx < 32 * 18; idx += 128) {
        int c = idx / 18, r = idx % 18;
        pw1s[r * 32 + c] = pw1[idx];
    }
    for (int idx = tid; idx < 32 * 96; idx += 128) {
        int c = idx / 96, r = idx % 96;
        pw2s[r * 32 + c] = pw2[idx];
        tw2s[r * 32 + c] = tw2[idx];
    }
    for (int idx = tid; idx < 32 * 36; idx += 128) {
        int c = idx / 36, r = idx % 36;
        tw1s[r * 32 + c] = tw1[idx];
    }
    __syncthreads();

    int w = tid >> 5, lane = tid & 31;
    int win = blockIdx.x * 4 + w;
    if (win >= BT) return;

    // ---------------- pressure encoder ----------------
    {
        const float* x = pressure + (size_t)win * (WW * NP);
        for (int idx = lane; idx < WW * NP; idx += 32) xs[w][idx] = x[idx];
        __syncwarp();

        float h1[18];
        float b1 = pb1[lane];
        #pragma unroll
        for (int l = 0; l < 18; l++) h1[l] = b1;
        #pragma unroll
        for (int i = 0; i < NP; i++) {
            float w0 = pw1s[(i * 3 + 0) * 32 + lane];
            float w1 = pw1s[(i * 3 + 1) * 32 + lane];
            float w2 = pw1s[(i * 3 + 2) * 32 + lane];
            #pragma unroll
            for (int lp = 0; lp < 20; lp++) {
                float xv = xs[w][lp * NP + i];
                if (lp < 18)              h1[lp]     += xv * w0;
                if (lp >= 1 && lp <= 18)  h1[lp - 1] += xv * w1;
                if (lp >= 2)              h1[lp - 2] += xv * w2;
            }
        }
        #pragma unroll
        for (int l = 0; l < 18; l++) h1s[w][l * 32 + lane] = fmaxf(h1[l], 0.f);
        __syncwarp();

        float acc[16];
        float b2 = pb2[lane];
        #pragma unroll
        for (int l = 0; l < 16; l++) acc[l] = b2;
        for (int ci = 0; ci < 32; ci++) {
            float w0 = pw2s[(ci * 3 + 0) * 32 + lane];
            float w1 = pw2s[(ci * 3 + 1) * 32 + lane];
            float w2 = pw2s[(ci * 3 + 2) * 32 + lane];
            #pragma unroll
            for (int lp = 0; lp < 18; lp++) {
                float hv = h1s[w][lp * 32 + ci];
                if (lp < 16)              acc[lp]     += hv * w0;
                if (lp >= 1 && lp <= 16)  acc[lp - 1] += hv * w1;
                if (lp >= 2)              acc[lp - 2] += hv * w2;
            }
        }
        float s = 0.f;
        #pragma unroll
        for (int l = 0; l < 16; l++) s += fmaxf(acc[l], 0.f);
        g_enc[(size_t)win * 64 + lane] = s * (1.f / 16.f);
        __syncwarp();
    }

    // ---------------- torque encoder ----------------
    {
        const float* x = torque + (size_t)win * (WW * NT);
        for (int idx = lane; idx < WW * NT; idx += 32) xs[w][idx] = x[idx];
        __syncwarp();

        float h1[18];
        float b1 = tb1[lane];
        #pragma unroll
        for (int l = 0; l < 18; l++) h1[l] = b1;
        #pragma unroll
        for (int i = 0; i < NT; i++) {
            float w0 = tw1s[(i * 3 + 0) * 32 + lane];
            float w1 = tw1s[(i * 3 + 1) * 32 + lane];
            float w2 = tw1s[(i * 3 + 2) * 32 + lane];
            #pragma unroll
            for (int lp = 0; lp < 20; lp++) {
                float xv = xs[w][lp * NT + i];
                if (lp < 18)              h1[lp]     += xv * w0;
                if (lp >= 1 && lp <= 18)  h1[lp - 1] += xv * w1;
                if (lp >= 2)              h1[lp - 2] += xv * w2;
            }
        }
        #pragma unroll
        for (int l = 0; l < 18; l++) h1s[w][l * 32 + lane] = fmaxf(h1[l], 0.f);
        __syncwarp();

        float acc[16];
        float b2 = tb2[lane];
        #pragma unroll
        for (int l = 0; l < 16; l++) acc[l] = b2;
        for (int ci = 0; ci < 32; ci++) {
            float w0 = tw2s[(ci * 3 + 0) * 32 + lane];
            float w1 = tw2s[(ci * 3 + 1) * 32 + lane];
            float w2 = tw2s[(ci * 3 + 2) * 32 + lane];
            #pragma unroll
            for (int lp = 0; lp < 18; lp++) {
                float hv = h1s[w][lp * 32 + ci];
                if (lp < 16)              acc[lp]     += hv * w0;
                if (lp >= 1 && lp <= 16)  acc[lp - 1] += hv * w1;
                if (lp >= 2)              acc[lp - 2] += hv * w2;
            }
        }
        float s = 0.f;
        #pragma unroll
        for (int l = 0; l < 16; l++) s += fmaxf(acc[l], 0.f);
        g_enc[(size_t)win * 64 + 32 + lane] = s * (1.f / 16.f);
    }
}

// =====================================================================
// Kernel 2: projection  feat = relu([pf,tf,ff] @ prw^T + prb)
// 4 windows per block, 64 output threads per window.
// =====================================================================
__global__ __launch_bounds__(256) void proj_kernel(
    const float* __restrict__ frag, const float* __restrict__ fw,
    const float* __restrict__ fb,   const float* __restrict__ prw,
    const float* __restrict__ prb)
{
    __shared__ float prws[72 * 64];   // [k][j]
    __shared__ float encs[4][64];
    __shared__ float ffs[4][8];

    int tid = threadIdx.x;
    for (int idx = tid; idx < 64 * 72; idx += 256) {
        int j = idx / 72, k = idx % 72;
        prws[k * 64 + j] = prw[idx];
    }
    int wloc = tid >> 6, j = tid & 63;
    int win = blockIdx.x * 4 + wloc;
    encs[wloc][j] = g_enc[(size_t)win * 64 + j];
    if (j < 8) {
        int b = win >> 8;
        ffs[wloc][j] = fmaxf(frag[b] * fw[j] + fb[j], 0.f);
    }
    __syncthreads();

    float acc = prb[j];
    #pragma unroll
    for (int k = 0; k < 64; k++) acc += encs[wloc][k] * prws[k * 64 + j];
    #pragma unroll
    for (int k = 0; k < 8; k++)  acc += ffs[wloc][k] * prws[(64 + k) * 64 + j];
    g_feat[(size_t)win * 64 + j] = fmaxf(acc, 0.f);
}

// =====================================================================
// Kernel 3: xg = feat @ Wih^T + (bih+bhh)     (16384,64)x(64,256)
// 16 windows per block, thread = one gate, M-register-blocked.
// Wih in 64 KB dynamic SMEM, transposed [k][g].
// =====================================================================
__global__ __launch_bounds__(256) void xg_kernel(
    const float* __restrict__ Wih, const float* __restrict__ bih,
    const float* __restrict__ bhh)
{
    extern __shared__ float wihs[];        // 64*256 floats
    __shared__ float feats[16][64];

    int tid = threadIdx.x;
    for (int idx = tid; idx < GATES * 64; idx += 256) {
        int g = idx / 64, k = idx % 64;
        wihs[k * GATES + g] = Wih[idx];
    }
    int base = blockIdx.x * 16;
    for (int idx = tid; idx < 16 * 64; idx += 256)
        feats[idx >> 6][idx & 63] = g_feat[(size_t)base * 64 + idx];
    __syncthreads();

    int g = tid;
    float bias = bih[g] + bhh[g];
    float acc[16];
    #pragma unroll
    for (int m = 0; m < 16; m++) acc[m] = bias;
    #pragma unroll 8
    for (int k = 0; k < 64; k++) {
        float wv = wihs[k * GATES + g];
        #pragma unroll
        for (int m = 0; m < 16; m++) acc[m] += feats[m][k] * wv;
    }
    #pragma unroll
    for (int m = 0; m < 16; m++)
        g_xg[(size_t)(base + m) * GATES + g] = acc[m];
}

// =====================================================================
// Kernel 4: LSTM recurrence. One block per batch row, 256 threads
// (thread = one gate). Whh transposed in 64 KB dynamic SMEM.
// =====================================================================
__global__ __launch_bounds__(256) void lstm_kernel(
    const float* __restrict__ Whh, float* __restrict__ outHT,
    float* __restrict__ outCT)
{
    extern __shared__ float ws[];          // 64*256, [k][g]
    __shared__ float hs[64], cs[64], gs[256];

    int tid = threadIdx.x;
    int b = blockIdx.x;
    for (int idx = tid; idx < GATES * 64; idx += 256) {
        int g = idx / 64, k = idx % 64;
        ws[k * GATES + g] = Whh[idx];
    }
    if (tid < 64) { hs[tid] = 0.f; cs[tid] = 0.f; }
    __syncthreads();

    const float* xg = g_xg + (size_t)b * TT * GATES;
    float* lo = g_lstm + (size_t)b * TT * PROJ;

    for (int t = 0; t < TT; t++) {
        float acc = xg[t * GATES + tid];       // issued early, consumed late
        float a0 = 0.f, a1 = 0.f, a2 = 0.f, a3 = 0.f;
        #pragma unroll
        for (int k = 0; k < 64; k += 4) {
            a0 += hs[k + 0] * ws[(k + 0) * GATES + tid];
            a1 += hs[k + 1] * ws[(k + 1) * GATES + tid];
            a2 += hs[k + 2] * ws[(k + 2) * GATES + tid];
            a3 += hs[k + 3] * ws[(k + 3) * GATES + tid];
        }
        gs[tid] = acc + (a0 + a1) + (a2 + a3);
        __syncthreads();
        if (tid < 64) {
            float iv = gs[tid], fv = gs[64 + tid];
            float gv = gs[128 + tid], ov = gs[192 + tid];
            float c = sigf(fv) * cs[tid] + sigf(iv) * tanhf(gv);
            float h = sigf(ov) * tanhf(c);
            cs[tid] = c; hs[tid] = h;
            lo[t * PROJ + tid] = h;
        }
        __syncthreads();
    }
    if (tid < 64) {
        outHT[b * 64 + tid] = hs[tid];
        outCT[b * 64 + tid] = cs[tid];
    }
}

// =====================================================================
// Kernel 5: head  out = sigmoid(lstm_out @ hw^T + hb)
// 64 windows per block, thread = (window, output).
// =====================================================================
__global__ __launch_bounds__(256) void head_kernel(
    const float* __restrict__ hw, const float* __restrict__ hb,
    float* __restrict__ out)
{
    __shared__ float tile[64][65];
    __shared__ float hws[4][64];

    int tid = threadIdx.x;
    int base = blockIdx.x * 64;
    for (int idx = tid; idx < 64 * 64; idx += 256)
        tile[idx >> 6][idx & 63] = g_lstm[(size_t)base * 64 + idx];
    hws[tid >> 6][tid & 63] = hw[tid];
    __syncthreads();

    int wl = tid >> 2, j = tid & 3;
    float acc = hb[j];
    #pragma unroll 8
    for (int k = 0; k < 64; k++) acc += tile[wl][k] * hws[j][k];
    out[(size_t)(base + wl) * 4 + j] = 1.f / (1.f + __expf(-acc));
}

// =====================================================================
extern "C" void kernel_launch(void* const* d_in, const int* in_sizes, int n_in,
                              void* d_out, int out_size)
{
    const float* pressure = (const float*)d_in[0];
    const float* torque   = (const float*)d_in[1];
    const float* frag     = (const float*)d_in[2];
    const float* pw1 = (const float*)d_in[3];
    const float* pb1 = (const float*)d_in[4];
    const float* pw2 = (const float*)d_in[5];
    const float* pb2 = (const float*)d_in[6];
    const float* tw1 = (const float*)d_in[7];
    const float* tb1 = (const float*)d_in[8];
    const float* tw2 = (const float*)d_in[9];
    const float* tb2 = (const float*)d_in[10];
    const float* fw  = (const float*)d_in[11];
    const float* fb  = (const float*)d_in[12];
    const float* prw = (const float*)d_in[13];
    const float* prb = (const float*)d_in[14];
    const float* Wih = (const float*)d_in[15];
    const float* Whh = (const float*)d_in[16];
    const float* bih = (const float*)d_in[17];
    const float* bhh = (const float*)d_in[18];
    const float* hw  = (const float*)d_in[19];
    const float* hb  = (const float*)d_in[20];

    float* out   = (float*)d_out;
    float* outHT = out + BB * TT * 4;            // 65536
    float* outCT = outHT + BB * PROJ;            // +4096

    // opt-in to >48KB dynamic shared memory (idempotent, deterministic)
    cudaFuncSetAttribute(xg_kernel,  cudaFuncAttributeMaxDynamicSharedMemorySize, 65536);
    cudaFuncSetAttribute(lstm_kernel, cudaFuncAttributeMaxDynamicSharedMemorySize, 65536);

    enc_kernel<<<BT / 4, 128>>>(pressure, torque, pw1, pb1, pw2, pb2,
                                tw1, tb1, tw2, tb2);
    proj_kernel<<<BT / 4, 256>>>(frag, fw, fb, prw, prb);
    xg_kernel<<<BT / 16, 256, 65536>>>(Wih, bih, bhh);
    lstm_kernel<<<BB, 256, 65536>>>(Whh, outHT, outCT);
    head_kernel<<<BT / 64, 256>>>(hw, hb, out);
}

// round 4
// speedup vs baseline: 1.1924x; 1.1924x over previous
#include <cuda_runtime.h>
#include <cstdint>

// ---------------- problem constants ----------------
#define BB 64
#define TT 256
#define BT (BB*TT)          // 16384 windows
#define WW 20
#define NP 6
#define NT 12
#define CH 32
#define FRAG 8
#define PROJ 64
#define GATES 256           // 4*PROJ

typedef unsigned long long ull;

// ---------------- scratch (static device memory; no allocs allowed) -------
__device__ float g_enc[BT * 64];      // [win][0:32]=pf, [32:64]=tf
__device__ float g_feat[BT * PROJ];
__device__ float g_xg[BT * GATES];
__device__ float g_lstm[BT * PROJ];

__device__ __forceinline__ float sigf(float x) {
    return 1.0f / (1.0f + __expf(-x));
}

// ---------------- packed f32x2 helpers (sm_103a) ----------------
__device__ __forceinline__ ull pk2(float a, float b) {
    ull d;
    asm("mov.b64 %0, {%1, %2};" : "=l"(d)
        : "r"(__float_as_uint(a)), "r"(__float_as_uint(b)));
    return d;
}
__device__ __forceinline__ ull bc2(float a) { return pk2(a, a); }
__device__ __forceinline__ void upk(float& a, float& b, ull p) {
    unsigned ua, ub;
    asm("mov.b64 {%0, %1}, %2;" : "=r"(ua), "=r"(ub) : "l"(p));
    a = __uint_as_float(ua); b = __uint_as_float(ub);
}
__device__ __forceinline__ ull fma2(ull a, ull b, ull c) {
    ull d;
    asm("fma.rn.f32x2 %0, %1, %2, %3;" : "=l"(d) : "l"(a), "l"(b), "l"(c));
    return d;
}

// =====================================================================
// Kernel 1: conv encoders, warp-per-window, packed-f32x2 math.
// Tap mapping (conv length-3, valid):
//   accE[m] (even pairs, outputs 2m,2m+1): tap0 <- x2[m], tap2 <- x2[m+1]
//   accO[m] = sum x2[m]*w1 for ALL m:  .lo -> h[2m-1], .hi -> h[2m]
// merge: h[2m] = accE[m].lo + accO[m].hi ; h[2m+1] = accE[m].hi + accO[m+1].lo
// (accO[0].lo and accO[last].hi fall outside the valid range and are unused.)
// =====================================================================
template<int CIN>
__device__ __forceinline__ float encode_one(
    const float* __restrict__ xglob,
    const float* __restrict__ w1s, const float* __restrict__ w2s,
    float b1, float b2, float* xs, float* h1s, int lane)
{
    // stage input transposed: global idx = lp*CIN + i  ->  xs[i*20 + lp]
    for (int idx = lane; idx < CIN * 20; idx += 32) {
        int lp = idx / CIN, i = idx % CIN;
        xs[i * 20 + lp] = xglob[idx];
    }
    __syncwarp();

    // ---- conv1: CIN -> 32, L 20 -> 18 ----
    ull accE[9], accO[10];
    {
        ull bp = bc2(b1);
        #pragma unroll
        for (int m = 0; m < 9; m++)  accE[m] = bp;
        #pragma unroll
        for (int m = 0; m < 10; m++) accO[m] = 0ull;
    }
    #pragma unroll
    for (int i = 0; i < CIN; i++) {
        const float* xr = xs + i * 20;
        ull x2[10];
        #pragma unroll
        for (int m = 0; m < 10; m++) x2[m] = *(const ull*)(xr + 2 * m);
        ull w0 = bc2(w1s[(i * 3 + 0) * 32 + lane]);
        ull w1 = bc2(w1s[(i * 3 + 1) * 32 + lane]);
        ull w2 = bc2(w1s[(i * 3 + 2) * 32 + lane]);
        #pragma unroll
        for (int m = 0; m < 9; m++)  accE[m] = fma2(x2[m], w0, accE[m]);
        #pragma unroll
        for (int m = 0; m < 10; m++) accO[m] = fma2(x2[m], w1, accO[m]);
        #pragma unroll
        for (int m = 1; m < 10; m++) accE[m - 1] = fma2(x2[m], w2, accE[m - 1]);
    }
    // merge + relu + store transposed row for conv2
    {
        float el[9], eh[9], ol[10], oh[10], h[18];
        #pragma unroll
        for (int m = 0; m < 9; m++)  upk(el[m], eh[m], accE[m]);
        #pragma unroll
        for (int m = 0; m < 10; m++) upk(ol[m], oh[m], accO[m]);
        #pragma unroll
        for (int m = 0; m < 9; m++) {
            h[2 * m]     = el[m] + oh[m];
            h[2 * m + 1] = eh[m] + ol[m + 1];
        }
        #pragma unroll
        for (int l = 0; l < 18; l++) h1s[lane * 22 + l] = fmaxf(h[l], 0.f);
    }
    __syncwarp();

    // ---- conv2: 32 -> 32, L 18 -> 16, then avg pool ----
    ull aE[8], aO[9];
    {
        ull bp = bc2(b2);
        #pragma unroll
        for (int m = 0; m < 8; m++) aE[m] = bp;
        #pragma unroll
        for (int m = 0; m < 9; m++) aO[m] = 0ull;
    }
    #pragma unroll 8
    for (int ci = 0; ci < 32; ci++) {
        const float* hr = h1s + ci * 22;
        ull x2[9];
        #pragma unroll
        for (int m = 0; m < 9; m++) x2[m] = *(const ull*)(hr + 2 * m);
        ull w0 = bc2(w2s[(ci * 3 + 0) * 32 + lane]);
        ull w1 = bc2(w2s[(ci * 3 + 1) * 32 + lane]);
        ull w2 = bc2(w2s[(ci * 3 + 2) * 32 + lane]);
        #pragma unroll
        for (int m = 0; m < 8; m++) aE[m] = fma2(x2[m], w0, aE[m]);
        #pragma unroll
        for (int m = 0; m < 9; m++) aO[m] = fma2(x2[m], w1, aO[m]);
        #pragma unroll
        for (int m = 1; m < 9; m++) aE[m - 1] = fma2(x2[m], w2, aE[m - 1]);
    }
    float s = 0.f;
    {
        float el[8], eh[8], ol[9], oh[9], h[16];
        #pragma unroll
        for (int m = 0; m < 8; m++) upk(el[m], eh[m], aE[m]);
        #pragma unroll
        for (int m = 0; m < 9; m++) upk(ol[m], oh[m], aO[m]);
        #pragma unroll
        for (int m = 0; m < 8; m++) {
            h[2 * m]     = el[m] + oh[m];
            h[2 * m + 1] = eh[m] + ol[m + 1];
        }
        #pragma unroll
        for (int l = 0; l < 16; l++) s += fmaxf(h[l], 0.f);
    }
    __syncwarp();
    return s * (1.f / 16.f);
}

__global__ __launch_bounds__(128) void enc_kernel(
    const float* __restrict__ pressure, const float* __restrict__ torque,
    const float* __restrict__ pw1, const float* __restrict__ pb1,
    const float* __restrict__ pw2, const float* __restrict__ pb2,
    const float* __restrict__ tw1, const float* __restrict__ tb1,
    const float* __restrict__ tw2, const float* __restrict__ tb2)
{
    __shared__ __align__(16) float pw1s[18 * 32];
    __shared__ __align__(16) float pw2s[96 * 32];
    __shared__ __align__(16) float tw1s[36 * 32];
    __shared__ __align__(16) float tw2s[96 * 32];
    __shared__ __align__(16) float xs[4][12 * 20];
    __shared__ __align__(16) float h1s[4][32 * 22];

    int tid = threadIdx.x;
    // weight staging, transposed: w[c][r] -> s[r*32+c]
    for (int idx = tid; idx < 32 * 18; idx += 128) {
        int c = idx / 18, r = idx % 18;
        pw1s[r * 32 + c] = pw1[idx];
    }
    for (int idx = tid; idx < 32 * 96; idx += 128) {
        int c = idx / 96, r = idx % 96;
        pw2s[r * 32 + c] = pw2[idx];
        tw2s[r * 32 + c] = tw2[idx];
    }
    for (int idx = tid; idx < 32 * 36; idx += 128) {
        int c = idx / 36, r = idx % 36;
        tw1s[r * 32 + c] = tw1[idx];
    }
    __syncthreads();

    int w = tid >> 5, lane = tid & 31;
    int win = blockIdx.x * 4 + w;

    float pf = encode_one<NP>(pressure + (size_t)win * (WW * NP),
                              pw1s, pw2s, pb1[lane], pb2[lane], xs[w], h1s[w], lane);
    g_enc[(size_t)win * 64 + lane] = pf;

    float tf = encode_one<NT>(torque + (size_t)win * (WW * NT),
                              tw1s, tw2s, tb1[lane], tb2[lane], xs[w], h1s[w], lane);
    g_enc[(size_t)win * 64 + 32 + lane] = tf;
}

// =====================================================================
// Kernel 2: projection  feat = relu([pf,tf,ff] @ prw^T + prb)
// =====================================================================
__global__ __launch_bounds__(256) void proj_kernel(
    const float* __restrict__ frag, const float* __restrict__ fw,
    const float* __restrict__ fb,   const float* __restrict__ prw,
    const float* __restrict__ prb)
{
    __shared__ float prws[72 * 64];   // [k][j]
    __shared__ float encs[4][64];
    __shared__ float ffs[4][8];

    int tid = threadIdx.x;
    for (int idx = tid; idx < 64 * 72; idx += 256) {
        int j = idx / 72, k = idx % 72;
        prws[k * 64 + j] = prw[idx];
    }
    int wloc = tid >> 6, j = tid & 63;
    int win = blockIdx.x * 4 + wloc;
    encs[wloc][j] = g_enc[(size_t)win * 64 + j];
    if (j < 8) {
        int b = win >> 8;
        ffs[wloc][j] = fmaxf(frag[b] * fw[j] + fb[j], 0.f);
    }
    __syncthreads();

    float acc = prb[j];
    #pragma unroll
    for (int k = 0; k < 64; k++) acc += encs[wloc][k] * prws[k * 64 + j];
    #pragma unroll
    for (int k = 0; k < 8; k++)  acc += ffs[wloc][k] * prws[(64 + k) * 64 + j];
    g_feat[(size_t)win * 64 + j] = fmaxf(acc, 0.f);
}

// =====================================================================
// Kernel 3: xg = feat @ Wih^T + (bih+bhh)
// =====================================================================
__global__ __launch_bounds__(256) void xg_kernel(
    const float* __restrict__ Wih, const float* __restrict__ bih,
    const float* __restrict__ bhh)
{
    extern __shared__ float wihs[];        // 64*256 floats
    __shared__ float feats[16][64];

    int tid = threadIdx.x;
    for (int idx = tid; idx < GATES * 64; idx += 256) {
        int g = idx / 64, k = idx % 64;
        wihs[k * GATES + g] = Wih[idx];
    }
    int base = blockIdx.x * 16;
    for (int idx = tid; idx < 16 * 64; idx += 256)
        feats[idx >> 6][idx & 63] = g_feat[(size_t)base * 64 + idx];
    __syncthreads();

    int g = tid;
    float bias = bih[g] + bhh[g];
    float acc[16];
    #pragma unroll
    for (int m = 0; m < 16; m++) acc[m] = bias;
    #pragma unroll 8
    for (int k = 0; k < 64; k++) {
        float wv = wihs[k * GATES + g];
        #pragma unroll
        for (int m = 0; m < 16; m++) acc[m] += feats[m][k] * wv;
    }
    #pragma unroll
    for (int m = 0; m < 16; m++)
        g_xg[(size_t)(base + m) * GATES + g] = acc[m];
}

// =====================================================================
// Kernel 4: LSTM recurrence. One block per batch row, 256 threads.
// Whh row for each thread's gate lives in REGISTERS (time-invariant),
// packed as f32x2 pairs. Per step: 16 LDS.128 broadcast of h + 32 FFMA2.
// =====================================================================
__global__ __launch_bounds__(256) void lstm_kernel(
    const float* __restrict__ Whh, float* __restrict__ outHT,
    float* __restrict__ outCT)
{
    __shared__ __align__(16) float hs[64];
    __shared__ float cs[64];
    __shared__ float gs[256];

    int tid = threadIdx.x;
    int b = blockIdx.x;

    // thread tid owns gate tid: load Whh[tid][0:64] into packed registers
    ull wp[32];
    const float4* wr = (const float4*)(Whh + (size_t)tid * 64);
    #pragma unroll
    for (int m = 0; m < 16; m++) {
        float4 v = wr[m];
        wp[2 * m]     = pk2(v.x, v.y);
        wp[2 * m + 1] = pk2(v.z, v.w);
    }
    if (tid < 64) { hs[tid] = 0.f; cs[tid] = 0.f; }
    __syncthreads();

    const float* xg = g_xg + (size_t)b * TT * GATES;
    float* lo = g_lstm + (size_t)b * TT * PROJ;

    float xcur = xg[tid];
    for (int t = 0; t < TT; t++) {
        float xnext = (t + 1 < TT) ? xg[(t + 1) * GATES + tid] : 0.f;

        ull a0 = 0, a1 = 0, a2 = 0, a3 = 0;
        #pragma unroll
        for (int m = 0; m < 32; m += 4) {
            ulonglong2 hp0 = *(const ulonglong2*)(hs + 2 * m);      // h[2m..2m+3]
            ulonglong2 hp1 = *(const ulonglong2*)(hs + 2 * m + 4);  // h[2m+4..2m+7]
            a0 = fma2(hp0.x, wp[m],     a0);
            a1 = fma2(hp0.y, wp[m + 1], a1);
            a2 = fma2(hp1.x, wp[m + 2], a2);
            a3 = fma2(hp1.y, wp[m + 3], a3);
        }
        float s0, s1, s2, s3, s4, s5, s6, s7;
        upk(s0, s1, a0); upk(s2, s3, a1); upk(s4, s5, a2); upk(s6, s7, a3);
        gs[tid] = ((s0 + s1) + (s2 + s3)) + ((s4 + s5) + (s6 + s7)) + xcur;
        __syncthreads();

        if (tid < 64) {
            float iv = gs[tid], fv = gs[64 + tid];
            float gv = gs[128 + tid], ov = gs[192 + tid];
            float si = sigf(iv), sf = sigf(fv), so = sigf(ov);
            float c = sf * cs[tid] + si * tanhf(gv);
            float h = so * tanhf(c);
            cs[tid] = c; hs[tid] = h;
            lo[t * PROJ + tid] = h;
        }
        __syncthreads();
        xcur = xnext;
    }
    if (tid < 64) {
        outHT[b * 64 + tid] = hs[tid];
        outCT[b * 64 + tid] = cs[tid];
    }
}

// =====================================================================
// Kernel 5: head  out = sigmoid(lstm_out @ hw^T + hb)
// =====================================================================
__global__ __launch_bounds__(256) void head_kernel(
    const float* __restrict__ hw, const float* __restrict__ hb,
    float* __restrict__ out)
{
    __shared__ float tile[64][65];
    __shared__ float hws[4][64];

    int tid = threadIdx.x;
    int base = blockIdx.x * 64;
    for (int idx = tid; idx < 64 * 64; idx += 256)
        tile[idx >> 6][idx & 63] = g_lstm[(size_t)base * 64 + idx];
    hws[tid >> 6][tid & 63] = hw[tid];
    __syncthreads();

    int wl = tid >> 2, j = tid & 3;
    float acc = hb[j];
    #pragma unroll 8
    for (int k = 0; k < 64; k++) acc += tile[wl][k] * hws[j][k];
    out[(size_t)(base + wl) * 4 + j] = 1.f / (1.f + __expf(-acc));
}

// =====================================================================
extern "C" void kernel_launch(void* const* d_in, const int* in_sizes, int n_in,
                              void* d_out, int out_size)
{
    const float* pressure = (const float*)d_in[0];
    const float* torque   = (const float*)d_in[1];
    const float* frag     = (const float*)d_in[2];
    const float* pw1 = (const float*)d_in[3];
    const float* pb1 = (const float*)d_in[4];
    const float* pw2 = (const float*)d_in[5];
    const float* pb2 = (const float*)d_in[6];
    const float* tw1 = (const float*)d_in[7];
    const float* tb1 = (const float*)d_in[8];
    const float* tw2 = (const float*)d_in[9];
    const float* tb2 = (const float*)d_in[10];
    const float* fw  = (const float*)d_in[11];
    const float* fb  = (const float*)d_in[12];
    const float* prw = (const float*)d_in[13];
    const float* prb = (const float*)d_in[14];
    const float* Wih = (const float*)d_in[15];
    const float* Whh = (const float*)d_in[16];
    const float* bih = (const float*)d_in[17];
    const float* bhh = (const float*)d_in[18];
    const float* hw  = (const float*)d_in[19];
    const float* hb  = (const float*)d_in[20];

    float* out   = (float*)d_out;
    float* outHT = out + BB * TT * 4;            // 65536
    float* outCT = outHT + BB * PROJ;            // +4096

    cudaFuncSetAttribute(xg_kernel, cudaFuncAttributeMaxDynamicSharedMemorySize, 65536);

    enc_kernel<<<BT / 4, 128>>>(pressure, torque, pw1, pb1, pw2, pb2,
                                tw1, tb1, tw2, tb2);
    proj_kernel<<<BT / 4, 256>>>(frag, fw, fb, prw, prb);
    xg_kernel<<<BT / 16, 256, 65536>>>(Wih, bih, bhh);
    lstm_kernel<<<BB, 256>>>(Whh, outHT, outCT);
    head_kernel<<<BT / 64, 256>>>(hw, hb, out);
}

// round 5
// speedup vs baseline: 1.3702x; 1.1491x over previous
#include <cuda_runtime.h>
#include <cstdint>

// ---------------- problem constants ----------------
#define BB 64
#define TT 256
#define BT (BB*TT)          // 16384 windows
#define WW 20
#define NP 6
#define NT 12
#define CH 32
#define FRAG 8
#define PROJ 64
#define GATES 256           // 4*PROJ

typedef unsigned long long ull;

// ---------------- scratch (static device memory; no allocs allowed) -------
__device__ float g_enc[BT * 64];      // [win][0:32]=pf, [32:64]=tf
__device__ float g_feat[BT * PROJ];
__device__ float g_xg[BT * GATES];    // PERMUTED: [win][j*4+gate]
__device__ float g_lstm[BT * PROJ];

__device__ __forceinline__ float sigf(float x) {
    return 1.0f / (1.0f + __expf(-x));
}

// ---------------- packed f32x2 helpers (sm_103a) ----------------
__device__ __forceinline__ ull pk2(float a, float b) {
    ull d;
    asm("mov.b64 %0, {%1, %2};" : "=l"(d)
        : "r"(__float_as_uint(a)), "r"(__float_as_uint(b)));
    return d;
}
__device__ __forceinline__ ull bc2(float a) { return pk2(a, a); }
__device__ __forceinline__ void upk(float& a, float& b, ull p) {
    unsigned ua, ub;
    asm("mov.b64 {%0, %1}, %2;" : "=r"(ua), "=r"(ub) : "l"(p));
    a = __uint_as_float(ua); b = __uint_as_float(ub);
}
__device__ __forceinline__ ull fma2(ull a, ull b, ull c) {
    ull d;
    asm("fma.rn.f32x2 %0, %1, %2, %3;" : "=l"(d) : "l"(a), "l"(b), "l"(c));
    return d;
}

// =====================================================================
// Kernel 1: conv encoders, warp-per-window, packed-f32x2 math.
//   accE[m] (even pairs, outputs 2m,2m+1): tap0 <- x2[m], tap2 <- x2[m+1]
//   accO[m] = sum x2[m]*w1 (all m): .lo -> h[2m-1], .hi -> h[2m]
// merge: h[2m] = accE[m].lo + accO[m].hi ; h[2m+1] = accE[m].hi + accO[m+1].lo
// =====================================================================
template<int CIN>
__device__ __forceinline__ float encode_one(
    const float* __restrict__ xglob,
    const float* __restrict__ w1s, const float* __restrict__ w2s,
    float b1, float b2, float* xs, float* h1s, int lane)
{
    // stage input transposed: global idx = lp*CIN + i  ->  xs[i*20 + lp]
    for (int idx = lane; idx < CIN * 20; idx += 32) {
        int lp = idx / CIN, i = idx % CIN;
        xs[i * 20 + lp] = xglob[idx];
    }
    __syncwarp();

    // ---- conv1: CIN -> 32, L 20 -> 18 ----
    ull accE[9], accO[10];
    {
        ull bp = bc2(b1);
        #pragma unroll
        for (int m = 0; m < 9; m++)  accE[m] = bp;
        #pragma unroll
        for (int m = 0; m < 10; m++) accO[m] = 0ull;
    }
    #pragma unroll
    for (int i = 0; i < CIN; i++) {
        const float* xr = xs + i * 20;
        ull x2[10];
        #pragma unroll
        for (int m = 0; m < 10; m++) x2[m] = *(const ull*)(xr + 2 * m);
        ull w0 = bc2(w1s[(i * 3 + 0) * 32 + lane]);
        ull w1 = bc2(w1s[(i * 3 + 1) * 32 + lane]);
        ull w2 = bc2(w1s[(i * 3 + 2) * 32 + lane]);
        #pragma unroll
        for (int m = 0; m < 9; m++)  accE[m] = fma2(x2[m], w0, accE[m]);
        #pragma unroll
        for (int m = 0; m < 10; m++) accO[m] = fma2(x2[m], w1, accO[m]);
        #pragma unroll
        for (int m = 1; m < 10; m++) accE[m - 1] = fma2(x2[m], w2, accE[m - 1]);
    }
    // streaming merge + relu + paired store (STS.64) for conv2
    {
        float ol0, oh0;
        upk(ol0, oh0, accO[0]);
        #pragma unroll
        for (int m = 0; m < 9; m++) {
            float el, eh, ol1, oh1;
            upk(el, eh, accE[m]);
            upk(ol1, oh1, accO[m + 1]);
            float h0 = fmaxf(el + oh0, 0.f);
            float h1 = fmaxf(eh + ol1, 0.f);
            *(ull*)(h1s + lane * 22 + 2 * m) = pk2(h0, h1);
            oh0 = oh1;
        }
    }
    __syncwarp();

    // ---- conv2: 32 -> 32, L 18 -> 16, then avg pool ----
    ull aE[8], aO[9];
    {
        ull bp = bc2(b2);
        #pragma unroll
        for (int m = 0; m < 8; m++) aE[m] = bp;
        #pragma unroll
        for (int m = 0; m < 9; m++) aO[m] = 0ull;
    }
    #pragma unroll 8
    for (int ci = 0; ci < 32; ci++) {
        const float* hr = h1s + ci * 22;
        ull x2[9];
        #pragma unroll
        for (int m = 0; m < 9; m++) x2[m] = *(const ull*)(hr + 2 * m);
        ull w0 = bc2(w2s[(ci * 3 + 0) * 32 + lane]);
        ull w1 = bc2(w2s[(ci * 3 + 1) * 32 + lane]);
        ull w2 = bc2(w2s[(ci * 3 + 2) * 32 + lane]);
        #pragma unroll
        for (int m = 0; m < 8; m++) aE[m] = fma2(x2[m], w0, aE[m]);
        #pragma unroll
        for (int m = 0; m < 9; m++) aO[m] = fma2(x2[m], w1, aO[m]);
        #pragma unroll
        for (int m = 1; m < 9; m++) aE[m - 1] = fma2(x2[m], w2, aE[m - 1]);
    }
    float s = 0.f;
    {
        float ol0, oh0;
        upk(ol0, oh0, aO[0]);
        #pragma unroll
        for (int m = 0; m < 8; m++) {
            float el, eh, ol1, oh1;
            upk(el, eh, aE[m]);
            upk(ol1, oh1, aO[m + 1]);
            s += fmaxf(el + oh0, 0.f);
            s += fmaxf(eh + ol1, 0.f);
            oh0 = oh1;
        }
    }
    __syncwarp();
    return s * (1.f / 16.f);
}

__global__ __launch_bounds__(128) void enc_kernel(
    const float* __restrict__ pressure, const float* __restrict__ torque,
    const float* __restrict__ pw1, const float* __restrict__ pb1,
    const float* __restrict__ pw2, const float* __restrict__ pb2,
    const float* __restrict__ tw1, const float* __restrict__ tb1,
    const float* __restrict__ tw2, const float* __restrict__ tb2)
{
    __shared__ __align__(16) float pw1s[18 * 32];
    __shared__ __align__(16) float pw2s[96 * 32];
    __shared__ __align__(16) float tw1s[36 * 32];
    __shared__ __align__(16) float tw2s[96 * 32];
    __shared__ __align__(16) float xs[4][12 * 20];
    __shared__ __align__(16) float h1s[4][32 * 22];

    int tid = threadIdx.x;
    for (int idx = tid; idx < 32 * 18; idx += 128) {
        int c = idx / 18, r = idx % 18;
        pw1s[r * 32 + c] = pw1[idx];
    }
    for (int idx = tid; idx < 32 * 96; idx += 128) {
        int c = idx / 96, r = idx % 96;
        pw2s[r * 32 + c] = pw2[idx];
        tw2s[r * 32 + c] = tw2[idx];
    }
    for (int idx = tid; idx < 32 * 36; idx += 128) {
        int c = idx / 36, r = idx % 36;
        tw1s[r * 32 + c] = tw1[idx];
    }
    __syncthreads();

    int w = tid >> 5, lane = tid & 31;
    int win = blockIdx.x * 4 + w;

    float pf = encode_one<NP>(pressure + (size_t)win * (WW * NP),
                              pw1s, pw2s, pb1[lane], pb2[lane], xs[w], h1s[w], lane);
    g_enc[(size_t)win * 64 + lane] = pf;

    float tf = encode_one<NT>(torque + (size_t)win * (WW * NT),
                              tw1s, tw2s, tb1[lane], tb2[lane], xs[w], h1s[w], lane);
    g_enc[(size_t)win * 64 + 32 + lane] = tf;
}

// =====================================================================
// Kernel 2: projection — 16 windows per block (amortize 18KB staging).
// =====================================================================
__global__ __launch_bounds__(256) void proj_kernel(
    const float* __restrict__ frag, const float* __restrict__ fw,
    const float* __restrict__ fb,   const float* __restrict__ prw,
    const float* __restrict__ prb)
{
    __shared__ float prws[72 * 64];   // [k][j]
    __shared__ float encs[16][64];
    __shared__ float ffs[8];

    int tid = threadIdx.x;
    int base = blockIdx.x * 16;
    for (int idx = tid; idx < 64 * 72; idx += 256) {
        int j = idx / 72, k = idx % 72;
        prws[k * 64 + j] = prw[idx];
    }
    for (int idx = tid; idx < 16 * 64; idx += 256)
        encs[idx >> 6][idx & 63] = g_enc[(size_t)base * 64 + idx];
    if (tid < 8) {
        int b = base >> 8;            // 16 consecutive windows share batch
        ffs[tid] = fmaxf(frag[b] * fw[tid] + fb[tid], 0.f);
    }
    __syncthreads();

    int j = tid & 63, w0 = tid >> 6;
    float fsum = 0.f;
    #pragma unroll
    for (int k = 0; k < 8; k++) fsum += ffs[k] * prws[(64 + k) * 64 + j];
    float bias = prb[j] + fsum;

    #pragma unroll
    for (int w = 0; w < 4; w++) {
        int wl = w0 * 4 + w;
        float acc = bias;
        #pragma unroll
        for (int k = 0; k < 64; k++) acc += encs[wl][k] * prws[k * 64 + j];
        g_feat[(size_t)(base + wl) * 64 + j] = fmaxf(acc, 0.f);
    }
}

// =====================================================================
// Kernel 3: xg = feat @ Wih^T + (bih+bhh), stored PERMUTED [j*4+gate]
// =====================================================================
__global__ __launch_bounds__(256) void xg_kernel(
    const float* __restrict__ Wih, const float* __restrict__ bih,
    const float* __restrict__ bhh)
{
    extern __shared__ float wihs[];        // 64*256 floats
    __shared__ float feats[16][64];

    int tid = threadIdx.x;
    for (int idx = tid; idx < GATES * 64; idx += 256) {
        int g = idx / 64, k = idx % 64;
        wihs[k * GATES + g] = Wih[idx];
    }
    int base = blockIdx.x * 16;
    for (int idx = tid; idx < 16 * 64; idx += 256)
        feats[idx >> 6][idx & 63] = g_feat[(size_t)base * 64 + idx];
    __syncthreads();

    int g = tid;
    int gp = ((g & 63) << 2) | (g >> 6);   // [j*4 + gate]
    float bias = bih[g] + bhh[g];
    float acc[16];
    #pragma unroll
    for (int m = 0; m < 16; m++) acc[m] = bias;
    #pragma unroll 8
    for (int k = 0; k < 64; k++) {
        float wv = wihs[k * GATES + g];
        #pragma unroll
        for (int m = 0; m < 16; m++) acc[m] += feats[m][k] * wv;
    }
    #pragma unroll
    for (int m = 0; m < 16; m++)
        g_xg[(size_t)(base + m) * GATES + gp] = acc[m];
}

// =====================================================================
// Kernel 4: LSTM. thread = (hidden j = tid>>2, gate = tid&3).
// Whh row in registers; own-gate nonlinearity in parallel; quad shuffle;
// leader keeps c in register; ping-pong hs -> ONE barrier per step.
// =====================================================================
__device__ __forceinline__ void lstm_step(
    const float* __restrict__ hsrc, float* __restrict__ hdst,
    const ull* wp, float xcur, bool isg, bool lead, int j,
    float& creg, float& hlast, float* lo, int t)
{
    ull a0 = 0, a1 = 0, a2 = 0, a3 = 0;
    #pragma unroll
    for (int m = 0; m < 32; m += 4) {
        ulonglong2 hp0 = *(const ulonglong2*)(hsrc + 2 * m);
        ulonglong2 hp1 = *(const ulonglong2*)(hsrc + 2 * m + 4);
        a0 = fma2(hp0.x, wp[m],     a0);
        a1 = fma2(hp0.y, wp[m + 1], a1);
        a2 = fma2(hp1.x, wp[m + 2], a2);
        a3 = fma2(hp1.y, wp[m + 3], a3);
    }
    float s0, s1, s2, s3, s4, s5, s6, s7;
    upk(s0, s1, a0); upk(s2, s3, a1); upk(s4, s5, a2); upk(s6, s7, a3);
    float v = ((s0 + s1) + (s2 + s3)) + ((s4 + s5) + (s6 + s7)) + xcur;

    // own-gate activation (sig for i,f,o; tanh = 2*sig(2x)-1 for g)
    float vs = isg ? (2.f * v) : v;
    float sg = sigf(vs);
    float act = isg ? (2.f * sg - 1.f) : sg;

    float af = __shfl_down_sync(0xffffffffu, act, 1);
    float ag = __shfl_down_sync(0xffffffffu, act, 2);
    float ao = __shfl_down_sync(0xffffffffu, act, 3);

    if (lead) {
        float c = af * creg + act * ag;       // act = i_act for leader
        creg = c;
        float tc = 2.f * sigf(2.f * c) - 1.f; // tanh(c)
        float h = ao * tc;
        hlast = h;
        hdst[j] = h;
        lo[t * PROJ + j] = h;
    }
    __syncthreads();
}

__global__ __launch_bounds__(256) void lstm_kernel(
    const float* __restrict__ Whh, float* __restrict__ outHT,
    float* __restrict__ outCT)
{
    __shared__ __align__(16) float hsA[64];
    __shared__ __align__(16) float hsB[64];

    int tid = threadIdx.x;
    int b = blockIdx.x;
    int gate = tid & 3;
    int j = tid >> 2;
    bool isg = (gate == 2);
    bool lead = (gate == 0);

    // Whh row for (gate, j): row index = gate*64 + j
    ull wp[32];
    const float4* wr = (const float4*)(Whh + (size_t)(gate * 64 + j) * 64);
    #pragma unroll
    for (int m = 0; m < 16; m++) {
        float4 v = wr[m];
        wp[2 * m]     = pk2(v.x, v.y);
        wp[2 * m + 1] = pk2(v.z, v.w);
    }
    if (tid < 64) { hsA[tid] = 0.f; }
    float creg = 0.f, hlast = 0.f;
    __syncthreads();

    const float* xg = g_xg + (size_t)b * TT * GATES;
    float* lo = g_lstm + (size_t)b * TT * PROJ;

    float xcur = xg[tid];
    for (int t = 0; t < TT; t += 2) {
        float xn0 = xg[(t + 1) * GATES + tid];
        lstm_step(hsA, hsB, wp, xcur, isg, lead, j, creg, hlast, lo, t);
        float xn1 = (t + 2 < TT) ? xg[(t + 2) * GATES + tid] : 0.f;
        lstm_step(hsB, hsA, wp, xn0, isg, lead, j, creg, hlast, lo, t + 1);
        xcur = xn1;
    }
    if (lead) {
        outHT[b * 64 + j] = hlast;
        outCT[b * 64 + j] = creg;
    }
}

// =====================================================================
// Kernel 5: head  out = sigmoid(lstm_out @ hw^T + hb)
// =====================================================================
__global__ __launch_bounds__(256) void head_kernel(
    const float* __restrict__ hw, const float* __restrict__ hb,
    float* __restrict__ out)
{
    __shared__ float tile[64][65];
    __shared__ float hws[4][64];

    int tid = threadIdx.x;
    int base = blockIdx.x * 64;
    for (int idx = tid; idx < 64 * 64; idx += 256)
        tile[idx >> 6][idx & 63] = g_lstm[(size_t)base * 64 + idx];
    hws[tid >> 6][tid & 63] = hw[tid];
    __syncthreads();

    int wl = tid >> 2, jj = tid & 3;
    float acc = hb[jj];
    #pragma unroll 8
    for (int k = 0; k < 64; k++) acc += tile[wl][k] * hws[jj][k];
    out[(size_t)(base + wl) * 4 + jj] = 1.f / (1.f + __expf(-acc));
}

// =====================================================================
extern "C" void kernel_launch(void* const* d_in, const int* in_sizes, int n_in,
                              void* d_out, int out_size)
{
    const float* pressure = (const float*)d_in[0];
    const float* torque   = (const float*)d_in[1];
    const float* frag     = (const float*)d_in[2];
    const float* pw1 = (const float*)d_in[3];
    const float* pb1 = (const float*)d_in[4];
    const float* pw2 = (const float*)d_in[5];
    const float* pb2 = (const float*)d_in[6];
    const float* tw1 = (const float*)d_in[7];
    const float* tb1 = (const float*)d_in[8];
    const float* tw2 = (const float*)d_in[9];
    const float* tb2 = (const float*)d_in[10];
    const float* fw  = (const float*)d_in[11];
    const float* fb  = (const float*)d_in[12];
    const float* prw = (const float*)d_in[13];
    const float* prb = (const float*)d_in[14];
    const float* Wih = (const float*)d_in[15];
    const float* Whh = (const float*)d_in[16];
    const float* bih = (const float*)d_in[17];
    const float* bhh = (const float*)d_in[18];
    const float* hw  = (const float*)d_in[19];
    const float* hb  = (const float*)d_in[20];

    float* out   = (float*)d_out;
    float* outHT = out + BB * TT * 4;            // 65536
    float* outCT = outHT + BB * PROJ;            // +4096

    cudaFuncSetAttribute(xg_kernel, cudaFuncAttributeMaxDynamicSharedMemorySize, 65536);

    enc_kernel<<<BT / 4, 128>>>(pressure, torque, pw1, pb1, pw2, pb2,
                                tw1, tb1, tw2, tb2);
    proj_kernel<<<BT / 16, 256>>>(frag, fw, fb, prw, prb);
    xg_kernel<<<BT / 16, 256, 65536>>>(Wih, bih, bhh);
    lstm_kernel<<<BB, 256>>>(Whh, outHT, outCT);
    head_kernel<<<BT / 64, 256>>>(hw, hb, out);
}

// round 6
// speedup vs baseline: 1.4693x; 1.0723x over previous
#include <cuda_runtime.h>
#include <cstdint>

// ---------------- problem constants ----------------
#define BB 64
#define TT 256
#define BT (BB*TT)          // 16384 windows
#define WW 20
#define NP 6
#define NT 12
#define CH 32
#define FRAG 8
#define PROJ 64
#define GATES 256           // 4*PROJ

typedef unsigned long long ull;

// ---------------- scratch (static device memory; no allocs allowed) -------
__device__ float g_enc[BT * 64];      // [win][0:32]=pf, [32:64]=tf
__device__ float g_xg[BT * GATES];    // PERMUTED: [win][j*4+gate]
__device__ float g_lstm[BT * PROJ];

// ---------------- MUFU-only activations (no FDIV on critical path) --------
__device__ __forceinline__ float ex2a(float x) {
    float y; asm("ex2.approx.ftz.f32 %0, %1;" : "=f"(y) : "f"(x)); return y;
}
__device__ __forceinline__ float rcpa(float x) {
    float y; asm("rcp.approx.ftz.f32 %0, %1;" : "=f"(y) : "f"(x)); return y;
}
#define NLOG2E -1.4426950408889634f
__device__ __forceinline__ float sigm(float x) {       // 1/(1+e^-x)
    return rcpa(1.f + ex2a(x * NLOG2E));
}
__device__ __forceinline__ float tanha(float x) {      // 2*sig(2x)-1
    return 2.f * rcpa(1.f + ex2a(x * (2.f * NLOG2E))) - 1.f;
}

// ---------------- packed f32x2 helpers (sm_103a) ----------------
__device__ __forceinline__ ull pk2(float a, float b) {
    ull d;
    asm("mov.b64 %0, {%1, %2};" : "=l"(d)
        : "r"(__float_as_uint(a)), "r"(__float_as_uint(b)));
    return d;
}
__device__ __forceinline__ ull bc2(float a) { return pk2(a, a); }
__device__ __forceinline__ void upk(float& a, float& b, ull p) {
    unsigned ua, ub;
    asm("mov.b64 {%0, %1}, %2;" : "=r"(ua), "=r"(ub) : "l"(p));
    a = __uint_as_float(ua); b = __uint_as_float(ub);
}
__device__ __forceinline__ ull fma2(ull a, ull b, ull c) {
    ull d;
    asm("fma.rn.f32x2 %0, %1, %2, %3;" : "=l"(d) : "l"(a), "l"(b), "l"(c));
    return d;
}
__device__ __forceinline__ ull add2(ull a, ull b) {
    ull d;
    asm("add.rn.f32x2 %0, %1, %2;" : "=l"(d) : "l"(a), "l"(b));
    return d;
}

// =====================================================================
// Kernel 1: conv encoders, warp-per-window, packed-f32x2 math.
// SMEM activation rows padded to 24 floats (96B, 16B-aligned) so all
// activation reads are LDS.128 broadcasts.
//   accE[m] (even pairs, outputs 2m,2m+1): tap0 <- x2[m], tap2 <- x2[m+1]
//   accO[m] = sum x2[m]*w1 (all m): .lo -> h[2m-1], .hi -> h[2m]
// =====================================================================
template<int CIN>
__device__ __forceinline__ float encode_one(
    const float* __restrict__ xglob,
    const float* __restrict__ w1s, const float* __restrict__ w2s,
    float b1, float b2, float* xs, float* h1s, int lane)
{
    // stage input transposed: global idx = lp*CIN + i  ->  xs[i*24 + lp]
    for (int idx = lane; idx < CIN * 20; idx += 32) {
        int lp = idx / CIN, i = idx % CIN;
        xs[i * 24 + lp] = xglob[idx];
    }
    __syncwarp();

    // ---- conv1: CIN -> 32, L 20 -> 18 ----
    ull accE[9], accO[10];
    {
        ull bp = bc2(b1);
        #pragma unroll
        for (int m = 0; m < 9; m++)  accE[m] = bp;
        #pragma unroll
        for (int m = 0; m < 10; m++) accO[m] = 0ull;
    }
    #pragma unroll
    for (int i = 0; i < CIN; i++) {
        const float* xr = xs + i * 24;
        ulonglong2 q0 = *(const ulonglong2*)(xr);
        ulonglong2 q1 = *(const ulonglong2*)(xr + 4);
        ulonglong2 q2 = *(const ulonglong2*)(xr + 8);
        ulonglong2 q3 = *(const ulonglong2*)(xr + 12);
        ulonglong2 q4 = *(const ulonglong2*)(xr + 16);
        ull x2[10] = {q0.x, q0.y, q1.x, q1.y, q2.x, q2.y, q3.x, q3.y, q4.x, q4.y};
        ull w0 = bc2(w1s[(i * 3 + 0) * 32 + lane]);
        ull w1 = bc2(w1s[(i * 3 + 1) * 32 + lane]);
        ull w2 = bc2(w1s[(i * 3 + 2) * 32 + lane]);
        #pragma unroll
        for (int m = 0; m < 9; m++)  accE[m] = fma2(x2[m], w0, accE[m]);
        #pragma unroll
        for (int m = 0; m < 10; m++) accO[m] = fma2(x2[m], w1, accO[m]);
        #pragma unroll
        for (int m = 1; m < 10; m++) accE[m - 1] = fma2(x2[m], w2, accE[m - 1]);
    }
    // streaming merge + relu + paired store for conv2
    {
        float ol0, oh0;
        upk(ol0, oh0, accO[0]);
        #pragma unroll
        for (int m = 0; m < 9; m++) {
            float el, eh, ol1, oh1;
            upk(el, eh, accE[m]);
            upk(ol1, oh1, accO[m + 1]);
            float h0 = fmaxf(el + oh0, 0.f);
            float h1 = fmaxf(eh + ol1, 0.f);
            *(ull*)(h1s + lane * 24 + 2 * m) = pk2(h0, h1);
            oh0 = oh1;
        }
    }
    __syncwarp();

    // ---- conv2: 32 -> 32, L 18 -> 16, then avg pool ----
    ull aE[8], aO[9];
    {
        ull bp = bc2(b2);
        #pragma unroll
        for (int m = 0; m < 8; m++) aE[m] = bp;
        #pragma unroll
        for (int m = 0; m < 9; m++) aO[m] = 0ull;
    }
    #pragma unroll 8
    for (int ci = 0; ci < 32; ci++) {
        const float* hr = h1s + ci * 24;
        ulonglong2 q0 = *(const ulonglong2*)(hr);
        ulonglong2 q1 = *(const ulonglong2*)(hr + 4);
        ulonglong2 q2 = *(const ulonglong2*)(hr + 8);
        ulonglong2 q3 = *(const ulonglong2*)(hr + 12);
        ull q4 = *(const ull*)(hr + 16);
        ull x2[9] = {q0.x, q0.y, q1.x, q1.y, q2.x, q2.y, q3.x, q3.y, q4};
        ull w0 = bc2(w2s[(ci * 3 + 0) * 32 + lane]);
        ull w1 = bc2(w2s[(ci * 3 + 1) * 32 + lane]);
        ull w2 = bc2(w2s[(ci * 3 + 2) * 32 + lane]);
        #pragma unroll
        for (int m = 0; m < 8; m++) aE[m] = fma2(x2[m], w0, aE[m]);
        #pragma unroll
        for (int m = 0; m < 9; m++) aO[m] = fma2(x2[m], w1, aO[m]);
        #pragma unroll
        for (int m = 1; m < 9; m++) aE[m - 1] = fma2(x2[m], w2, aE[m - 1]);
    }
    float s = 0.f;
    {
        float ol0, oh0;
        upk(ol0, oh0, aO[0]);
        #pragma unroll
        for (int m = 0; m < 8; m++) {
            float el, eh, ol1, oh1;
            upk(el, eh, aE[m]);
            upk(ol1, oh1, aO[m + 1]);
            s += fmaxf(el + oh0, 0.f);
            s += fmaxf(eh + ol1, 0.f);
            oh0 = oh1;
        }
    }
    __syncwarp();
    return s * (1.f / 16.f);
}

__global__ __launch_bounds__(128) void enc_kernel(
    const float* __restrict__ pressure, const float* __restrict__ torque,
    const float* __restrict__ pw1, const float* __restrict__ pb1,
    const float* __restrict__ pw2, const float* __restrict__ pb2,
    const float* __restrict__ tw1, const float* __restrict__ tb1,
    const float* __restrict__ tw2, const float* __restrict__ tb2)
{
    __shared__ __align__(16) float pw1s[18 * 32];
    __shared__ __align__(16) float pw2s[96 * 32];
    __shared__ __align__(16) float tw1s[36 * 32];
    __shared__ __align__(16) float tw2s[96 * 32];
    __shared__ __align__(16) float xs[4][12 * 24];
    __shared__ __align__(16) float h1s[4][32 * 24];

    int tid = threadIdx.x;
    for (int idx = tid; idx < 32 * 18; idx += 128) {
        int c = idx / 18, r = idx % 18;
        pw1s[r * 32 + c] = pw1[idx];
    }
    for (int idx = tid; idx < 32 * 96; idx += 128) {
        int c = idx / 96, r = idx % 96;
        pw2s[r * 32 + c] = pw2[idx];
        tw2s[r * 32 + c] = tw2[idx];
    }
    for (int idx = tid; idx < 32 * 36; idx += 128) {
        int c = idx / 36, r = idx % 36;
        tw1s[r * 32 + c] = tw1[idx];
    }
    __syncthreads();

    int w = tid >> 5, lane = tid & 31;
    int win = blockIdx.x * 4 + w;

    float pf = encode_one<NP>(pressure + (size_t)win * (WW * NP),
                              pw1s, pw2s, pb1[lane], pb2[lane], xs[w], h1s[w], lane);
    g_enc[(size_t)win * 64 + lane] = pf;

    float tf = encode_one<NT>(torque + (size_t)win * (WW * NT),
                              tw1s, tw2s, tb1[lane], tb2[lane], xs[w], h1s[w], lane);
    g_enc[(size_t)win * 64 + 32 + lane] = tf;
}

// =====================================================================
// Kernel 2: FUSED projection + xg. 16 windows per block.
//   feat = relu([pf,tf,ff] @ prw^T + prb)   (kept in SMEM only)
//   xg   = feat @ Wih^T + (bih+bhh), stored PERMUTED [j*4+gate]
// =====================================================================
__global__ __launch_bounds__(256) void projxg_kernel(
    const float* __restrict__ frag, const float* __restrict__ fw,
    const float* __restrict__ fb,   const float* __restrict__ prw,
    const float* __restrict__ prb,  const float* __restrict__ Wih,
    const float* __restrict__ bih,  const float* __restrict__ bhh)
{
    extern __shared__ float sm[];
    float* wihs  = sm;                      // 64*256 = 16384  [k][g]
    float* prws  = sm + 16384;              // 72*64  = 4608   [k][j]
    float* encs  = sm + 16384 + 4608;       // 16*64  = 1024
    float* feats = encs + 1024;             // 16*64  = 1024
    float* ffs   = feats + 1024;            // 8

    int tid = threadIdx.x;
    int base = blockIdx.x * 16;

    for (int idx = tid; idx < GATES * 64; idx += 256) {
        int g = idx / 64, k = idx % 64;
        wihs[k * GATES + g] = Wih[idx];
    }
    for (int idx = tid; idx < 64 * 72; idx += 256) {
        int j = idx / 72, k = idx % 72;
        prws[k * 64 + j] = prw[idx];
    }
    for (int idx = tid; idx < 16 * 64; idx += 256)
        encs[idx] = g_enc[(size_t)base * 64 + idx];
    if (tid < 8) {
        int b = base >> 8;                  // 16 consecutive windows share batch
        ffs[tid] = fmaxf(frag[b] * fw[tid] + fb[tid], 0.f);
    }
    __syncthreads();

    // --- phase 1: projection into SMEM ---
    {
        int j = tid & 63, w0 = tid >> 6;
        float fsum = 0.f;
        #pragma unroll
        for (int k = 0; k < 8; k++) fsum += ffs[k] * prws[(64 + k) * 64 + j];
        float bias = prb[j] + fsum;
        #pragma unroll
        for (int w = 0; w < 4; w++) {
            int wl = w0 * 4 + w;
            float acc = bias;
            #pragma unroll
            for (int k = 0; k < 64; k++) acc += encs[wl * 64 + k] * prws[k * 64 + j];
            feats[wl * 64 + j] = fmaxf(acc, 0.f);
        }
    }
    __syncthreads();

    // --- phase 2: xg GEMM ---
    int g = tid;
    int gp = ((g & 63) << 2) | (g >> 6);   // [j*4 + gate]
    float bias = bih[g] + bhh[g];
    float acc[16];
    #pragma unroll
    for (int m = 0; m < 16; m++) acc[m] = bias;
    #pragma unroll 8
    for (int k = 0; k < 64; k++) {
        float wv = wihs[k * GATES + g];
        #pragma unroll
        for (int m = 0; m < 16; m++) acc[m] += feats[m * 64 + k] * wv;
    }
    #pragma unroll
    for (int m = 0; m < 16; m++)
        g_xg[(size_t)(base + m) * GATES + gp] = acc[m];
}

// =====================================================================
// Kernel 3: LSTM. thread = (hidden j = tid>>2, gate = tid&3).
// Whh row in registers; MUFU-only activations; quad shuffle; leader
// keeps c in register; ping-pong hs; ONE barrier/step; xg prefetched
// FOUR steps ahead (covers DRAM latency of the streaming xg reads).
// =====================================================================
__device__ __forceinline__ void lstm_step(
    const float* __restrict__ hsrc, float* __restrict__ hdst,
    const ull* wp, float xcur, bool isg, bool lead, int j,
    float& creg, float& hlast, float* lo, int t)
{
    ull a0 = 0, a1 = 0, a2 = 0, a3 = 0;
    #pragma unroll
    for (int m = 0; m < 32; m += 4) {
        ulonglong2 hp0 = *(const ulonglong2*)(hsrc + 2 * m);
        ulonglong2 hp1 = *(const ulonglong2*)(hsrc + 2 * m + 4);
        a0 = fma2(hp0.x, wp[m],     a0);
        a1 = fma2(hp0.y, wp[m + 1], a1);
        a2 = fma2(hp1.x, wp[m + 2], a2);
        a3 = fma2(hp1.y, wp[m + 3], a3);
    }
    a0 = add2(a0, a1);
    a2 = add2(a2, a3);
    a0 = add2(a0, a2);
    float slo, shi;
    upk(slo, shi, a0);
    float v = slo + shi + xcur;

    // own-gate activation: sig for i,f,o ; tanh for g (all MUFU)
    float scale = isg ? (2.f * NLOG2E) : NLOG2E;
    float r = rcpa(1.f + ex2a(v * scale));
    float act = isg ? (2.f * r - 1.f) : r;

    float af = __shfl_down_sync(0xffffffffu, act, 1);
    float ag = __shfl_down_sync(0xffffffffu, act, 2);
    float ao = __shfl_down_sync(0xffffffffu, act, 3);

    if (lead) {
        float c = af * creg + act * ag;       // act = i_act for leader
        creg = c;
        float h = ao * tanha(c);
        hlast = h;
        hdst[j] = h;
        lo[t * PROJ + j] = h;
    }
    __syncthreads();
}

__global__ __launch_bounds__(256) void lstm_kernel(
    const float* __restrict__ Whh, float* __restrict__ outHT,
    float* __restrict__ outCT)
{
    __shared__ __align__(16) float hsA[64];
    __shared__ __align__(16) float hsB[64];

    int tid = threadIdx.x;
    int b = blockIdx.x;
    int gate = tid & 3;
    int j = tid >> 2;
    bool isg = (gate == 2);
    bool lead = (gate == 0);

    // Whh row for (gate, j): row index = gate*64 + j
    ull wp[32];
    const float4* wr = (const float4*)(Whh + (size_t)(gate * 64 + j) * 64);
    #pragma unroll
    for (int m = 0; m < 16; m++) {
        float4 v = wr[m];
        wp[2 * m]     = pk2(v.x, v.y);
        wp[2 * m + 1] = pk2(v.z, v.w);
    }
    if (tid < 64) { hsA[tid] = 0.f; }
    float creg = 0.f, hlast = 0.f;
    __syncthreads();

    const float* xg = g_xg + (size_t)b * TT * GATES;
    float* lo = g_lstm + (size_t)b * TT * PROJ;

    // prefetch ring, depth 4
    float xq0 = xg[0 * GATES + tid];
    float xq1 = xg[1 * GATES + tid];
    float xq2 = xg[2 * GATES + tid];
    float xq3 = xg[3 * GATES + tid];

    for (int t = 0; t < TT; t += 4) {
        int tn = t + 4;
        bool more = (tn < TT);
        lstm_step(hsA, hsB, wp, xq0, isg, lead, j, creg, hlast, lo, t);
        xq0 = more ? xg[(tn + 0) * GATES + tid] : 0.f;
        lstm_step(hsB, hsA, wp, xq1, isg, lead, j, creg, hlast, lo, t + 1);
        xq1 = more ? xg[(tn + 1) * GATES + tid] : 0.f;
        lstm_step(hsA, hsB, wp, xq2, isg, lead, j, creg, hlast, lo, t + 2);
        xq2 = more ? xg[(tn + 2) * GATES + tid] : 0.f;
        lstm_step(hsB, hsA, wp, xq3, isg, lead, j, creg, hlast, lo, t + 3);
        xq3 = more ? xg[(tn + 3) * GATES + tid] : 0.f;
    }
    if (lead) {
        outHT[b * 64 + j] = hlast;
        outCT[b * 64 + j] = creg;
    }
}

// =====================================================================
// Kernel 4: head  out = sigmoid(lstm_out @ hw^T + hb)
// =====================================================================
__global__ __launch_bounds__(256) void head_kernel(
    const float* __restrict__ hw, const float* __restrict__ hb,
    float* __restrict__ out)
{
    __shared__ float tile[64][65];
    __shared__ float hws[4][64];

    int tid = threadIdx.x;
    int base = blockIdx.x * 64;
    for (int idx = tid; idx < 64 * 64; idx += 256)
        tile[idx >> 6][idx & 63] = g_lstm[(size_t)base * 64 + idx];
    hws[tid >> 6][tid & 63] = hw[tid];
    __syncthreads();

    int wl = tid >> 2, jj = tid & 3;
    float acc = hb[jj];
    #pragma unroll 8
    for (int k = 0; k < 64; k++) acc += tile[wl][k] * hws[jj][k];
    out[(size_t)(base + wl) * 4 + jj] = sigm(acc);
}

// =====================================================================
extern "C" void kernel_launch(void* const* d_in, const int* in_sizes, int n_in,
                              void* d_out, int out_size)
{
    const float* pressure = (const float*)d_in[0];
    const float* torque   = (const float*)d_in[1];
    const float* frag     = (const float*)d_in[2];
    const float* pw1 = (const float*)d_in[3];
    const float* pb1 = (const float*)d_in[4];
    const float* pw2 = (const float*)d_in[5];
    const float* pb2 = (const float*)d_in[6];
    const float* tw1 = (const float*)d_in[7];
    const float* tb1 = (const float*)d_in[8];
    const float* tw2 = (const float*)d_in[9];
    const float* tb2 = (const float*)d_in[10];
    const float* fw  = (const float*)d_in[11];
    const float* fb  = (const float*)d_in[12];
    const float* prw = (const float*)d_in[13];
    const float* prb = (const float*)d_in[14];
    const float* Wih = (const float*)d_in[15];
    const float* Whh = (const float*)d_in[16];
    const float* bih = (const float*)d_in[17];
    const float* bhh = (const float*)d_in[18];
    const float* hw  = (const float*)d_in[19];
    const float* hb  = (const float*)d_in[20];

    float* out   = (float*)d_out;
    float* outHT = out + BB * TT * 4;            // 65536
    float* outCT = outHT + BB * PROJ;            // +4096

    const int projxg_smem = (16384 + 4608 + 1024 + 1024 + 8) * 4;
    cudaFuncSetAttribute(projxg_kernel, cudaFuncAttributeMaxDynamicSharedMemorySize,
                         projxg_smem);

    enc_kernel<<<BT / 4, 128>>>(pressure, torque, pw1, pb1, pw2, pb2,
                                tw1, tb1, tw2, tb2);
    projxg_kernel<<<BT / 16, 256, projxg_smem>>>(frag, fw, fb, prw, prb,
                                                 Wih, bih, bhh);
    lstm_kernel<<<BB, 256>>>(Whh, outHT, outCT);
    head_kernel<<<BT / 64, 256>>>(hw, hb, out);
}

// round 7
// speedup vs baseline: 1.5079x; 1.0263x over previous
#include <cuda_runtime.h>
#include <cstdint>

// ---------------- problem constants ----------------
#define BB 64
#define TT 256
#define BT (BB*TT)          // 16384 windows
#define WW 20
#define NP 6
#define NT 12
#define CH 32
#define FRAG 8
#define PROJ 64
#define GATES 256           // 4*PROJ

typedef unsigned long long ull;

// ---------------- scratch (static device memory; no allocs allowed) -------
__device__ float g_enc[BT * 64];      // [win][0:32]=pf, [32:64]=tf
__device__ float g_xg[BT * GATES];    // PERMUTED: [win][j*4+gate]
__device__ float g_lstm[BT * PROJ];

// ---------------- MUFU-only activations ----------------
__device__ __forceinline__ float ex2a(float x) {
    float y; asm("ex2.approx.ftz.f32 %0, %1;" : "=f"(y) : "f"(x)); return y;
}
__device__ __forceinline__ float rcpa(float x) {
    float y; asm("rcp.approx.ftz.f32 %0, %1;" : "=f"(y) : "f"(x)); return y;
}
#define NLOG2E -1.4426950408889634f
__device__ __forceinline__ float sigm(float x) {       // 1/(1+e^-x)
    return rcpa(1.f + ex2a(x * NLOG2E));
}
__device__ __forceinline__ float tanha(float x) {      // 2*sig(2x)-1
    return 2.f * rcpa(1.f + ex2a(x * (2.f * NLOG2E))) - 1.f;
}

// ---------------- packed f32x2 helpers (sm_103a) ----------------
__device__ __forceinline__ ull pk2(float a, float b) {
    ull d;
    asm("mov.b64 %0, {%1, %2};" : "=l"(d)
        : "r"(__float_as_uint(a)), "r"(__float_as_uint(b)));
    return d;
}
__device__ __forceinline__ ull bc2(float a) { return pk2(a, a); }
__device__ __forceinline__ void upk(float& a, float& b, ull p) {
    unsigned ua, ub;
    asm("mov.b64 {%0, %1}, %2;" : "=r"(ua), "=r"(ub) : "l"(p));
    a = __uint_as_float(ua); b = __uint_as_float(ub);
}
__device__ __forceinline__ ull fma2(ull a, ull b, ull c) {
    ull d;
    asm("fma.rn.f32x2 %0, %1, %2, %3;" : "=l"(d) : "l"(a), "l"(b), "l"(c));
    return d;
}
__device__ __forceinline__ ull add2(ull a, ull b) {
    ull d;
    asm("add.rn.f32x2 %0, %1, %2;" : "=l"(d) : "l"(a), "l"(b));
    return d;
}

// ---------------- mbarrier / bulk-async helpers ----------------
__device__ __forceinline__ unsigned smem_u32(const void* p) {
    return (unsigned)__cvta_generic_to_shared(p);
}
__device__ __forceinline__ void mbar_init(unsigned a, unsigned cnt) {
    asm volatile("mbarrier.init.shared.b64 [%0], %1;" :: "r"(a), "r"(cnt) : "memory");
}
__device__ __forceinline__ void mbar_expect(unsigned a, unsigned bytes) {
    asm volatile("mbarrier.arrive.expect_tx.shared.b64 _, [%0], %1;"
        :: "r"(a), "r"(bytes) : "memory");
}
__device__ __forceinline__ void bulk_g2s(unsigned dst, const void* src,
                                         unsigned bytes, unsigned mbar) {
    asm volatile(
        "cp.async.bulk.shared::cluster.global.mbarrier::complete_tx::bytes "
        "[%0], [%1], %2, [%3];"
        :: "r"(dst), "l"(src), "r"(bytes), "r"(mbar) : "memory");
}
__device__ __forceinline__ void mbar_wait(unsigned a, unsigned parity) {
    asm volatile(
        "{\n\t.reg .pred P;\n"
        "WL_%=:\n\t"
        "mbarrier.try_wait.parity.acquire.cta.shared::cta.b64 P, [%0], %1;\n\t"
        "@!P bra WL_%=;\n\t}"
        :: "r"(a), "r"(parity) : "memory");
}

// =====================================================================
// Kernel 1: conv encoders, warp-per-window, packed-f32x2 math.
// =====================================================================
template<int CIN>
__device__ __forceinline__ float encode_one(
    const float* __restrict__ xglob,
    const float* __restrict__ w1s, const float* __restrict__ w2s,
    float b1, float b2, float* xs, float* h1s, int lane)
{
    for (int idx = lane; idx < CIN * 20; idx += 32) {
        int lp = idx / CIN, i = idx % CIN;
        xs[i * 24 + lp] = xglob[idx];
    }
    __syncwarp();

    // ---- conv1: CIN -> 32, L 20 -> 18 ----
    ull accE[9], accO[10];
    {
        ull bp = bc2(b1);
        #pragma unroll
        for (int m = 0; m < 9; m++)  accE[m] = bp;
        #pragma unroll
        for (int m = 0; m < 10; m++) accO[m] = 0ull;
    }
    #pragma unroll
    for (int i = 0; i < CIN; i++) {
        const float* xr = xs + i * 24;
        ulonglong2 q0 = *(const ulonglong2*)(xr);
        ulonglong2 q1 = *(const ulonglong2*)(xr + 4);
        ulonglong2 q2 = *(const ulonglong2*)(xr + 8);
        ulonglong2 q3 = *(const ulonglong2*)(xr + 12);
        ulonglong2 q4 = *(const ulonglong2*)(xr + 16);
        ull x2[10] = {q0.x, q0.y, q1.x, q1.y, q2.x, q2.y, q3.x, q3.y, q4.x, q4.y};
        ull w0 = bc2(w1s[(i * 3 + 0) * 32 + lane]);
        ull w1 = bc2(w1s[(i * 3 + 1) * 32 + lane]);
        ull w2 = bc2(w1s[(i * 3 + 2) * 32 + lane]);
        #pragma unroll
        for (int m = 0; m < 9; m++)  accE[m] = fma2(x2[m], w0, accE[m]);
        #pragma unroll
        for (int m = 0; m < 10; m++) accO[m] = fma2(x2[m], w1, accO[m]);
        #pragma unroll
        for (int m = 1; m < 10; m++) accE[m - 1] = fma2(x2[m], w2, accE[m - 1]);
    }
    {
        float ol0, oh0;
        upk(ol0, oh0, accO[0]);
        #pragma unroll
        for (int m = 0; m < 9; m++) {
            float el, eh, ol1, oh1;
            upk(el, eh, accE[m]);
            upk(ol1, oh1, accO[m + 1]);
            float h0 = fmaxf(el + oh0, 0.f);
            float h1 = fmaxf(eh + ol1, 0.f);
            *(ull*)(h1s + lane * 24 + 2 * m) = pk2(h0, h1);
            oh0 = oh1;
        }
    }
    __syncwarp();

    // ---- conv2: 32 -> 32, L 18 -> 16, then avg pool ----
    ull aE[8], aO[9];
    {
        ull bp = bc2(b2);
        #pragma unroll
        for (int m = 0; m < 8; m++) aE[m] = bp;
        #pragma unroll
        for (int m = 0; m < 9; m++) aO[m] = 0ull;
    }
    #pragma unroll 8
    for (int ci = 0; ci < 32; ci++) {
        const float* hr = h1s + ci * 24;
        ulonglong2 q0 = *(const ulonglong2*)(hr);
        ulonglong2 q1 = *(const ulonglong2*)(hr + 4);
        ulonglong2 q2 = *(const ulonglong2*)(hr + 8);
        ulonglong2 q3 = *(const ulonglong2*)(hr + 12);
        ull q4 = *(const ull*)(hr + 16);
        ull x2[9] = {q0.x, q0.y, q1.x, q1.y, q2.x, q2.y, q3.x, q3.y, q4};
        ull w0 = bc2(w2s[(ci * 3 + 0) * 32 + lane]);
        ull w1 = bc2(w2s[(ci * 3 + 1) * 32 + lane]);
        ull w2 = bc2(w2s[(ci * 3 + 2) * 32 + lane]);
        #pragma unroll
        for (int m = 0; m < 8; m++) aE[m] = fma2(x2[m], w0, aE[m]);
        #pragma unroll
        for (int m = 0; m < 9; m++) aO[m] = fma2(x2[m], w1, aO[m]);
        #pragma unroll
        for (int m = 1; m < 9; m++) aE[m - 1] = fma2(x2[m], w2, aE[m - 1]);
    }
    float s = 0.f;
    {
        float ol0, oh0;
        upk(ol0, oh0, aO[0]);
        #pragma unroll
        for (int m = 0; m < 8; m++) {
            float el, eh, ol1, oh1;
            upk(el, eh, aE[m]);
            upk(ol1, oh1, aO[m + 1]);
            s += fmaxf(el + oh0, 0.f);
            s += fmaxf(eh + ol1, 0.f);
            oh0 = oh1;
        }
    }
    __syncwarp();
    return s * (1.f / 16.f);
}

__global__ __launch_bounds__(128, 4) void enc_kernel(
    const float* __restrict__ pressure, const float* __restrict__ torque,
    const float* __restrict__ pw1, const float* __restrict__ pb1,
    const float* __restrict__ pw2, const float* __restrict__ pb2,
    const float* __restrict__ tw1, const float* __restrict__ tb1,
    const float* __restrict__ tw2, const float* __restrict__ tb2)
{
    __shared__ __align__(16) float pw1s[18 * 32];
    __shared__ __align__(16) float pw2s[96 * 32];
    __shared__ __align__(16) float tw1s[36 * 32];
    __shared__ __align__(16) float tw2s[96 * 32];
    __shared__ __align__(16) float xs[4][12 * 24];
    __shared__ __align__(16) float h1s[4][32 * 24];

    int tid = threadIdx.x;
    for (int idx = tid; idx < 32 * 18; idx += 128) {
        int c = idx / 18, r = idx % 18;
        pw1s[r * 32 + c] = pw1[idx];
    }
    for (int idx = tid; idx < 32 * 96; idx += 128) {
        int c = idx / 96, r = idx % 96;
        pw2s[r * 32 + c] = pw2[idx];
        tw2s[r * 32 + c] = tw2[idx];
    }
    for (int idx = tid; idx < 32 * 36; idx += 128) {
        int c = idx / 36, r = idx % 36;
        tw1s[r * 32 + c] = tw1[idx];
    }
    __syncthreads();

    int w = tid >> 5, lane = tid & 31;
    int win = blockIdx.x * 4 + w;

    float pf = encode_one<NP>(pressure + (size_t)win * (WW * NP),
                              pw1s, pw2s, pb1[lane], pb2[lane], xs[w], h1s[w], lane);
    g_enc[(size_t)win * 64 + lane] = pf;

    float tf = encode_one<NT>(torque + (size_t)win * (WW * NT),
                              tw1s, tw2s, tb1[lane], tb2[lane], xs[w], h1s[w], lane);
    g_enc[(size_t)win * 64 + 32 + lane] = tf;
}

// =====================================================================
// Kernel 2: FUSED projection + xg. 16 windows per block.
//   feat kept in SMEM TRANSPOSED [k][m] (reads are broadcast),
//   xg phase runs packed f32x2 over window pairs.
// =====================================================================
__global__ __launch_bounds__(256) void projxg_kernel(
    const float* __restrict__ frag, const float* __restrict__ fw,
    const float* __restrict__ fb,   const float* __restrict__ prw,
    const float* __restrict__ prb,  const float* __restrict__ Wih,
    const float* __restrict__ bih,  const float* __restrict__ bhh)
{
    extern __shared__ __align__(16) float sm[];
    float* wihs   = sm;                     // 64*256 = 16384  [k][g]
    float* prws   = sm + 16384;             // 72*64  = 4608   [k][j]
    float* encs   = sm + 16384 + 4608;      // 16*64  = 1024
    float* featsT = encs + 1024;            // 64*16  = 1024   [k][m]
    float* ffs    = featsT + 1024;          // 8

    int tid = threadIdx.x;
    int base = blockIdx.x * 16;

    for (int idx = tid; idx < GATES * 64; idx += 256) {
        int g = idx / 64, k = idx % 64;
        wihs[k * GATES + g] = Wih[idx];
    }
    for (int idx = tid; idx < 64 * 72; idx += 256) {
        int j = idx / 72, k = idx % 72;
        prws[k * 64 + j] = prw[idx];
    }
    for (int idx = tid; idx < 16 * 64; idx += 256)
        encs[idx] = g_enc[(size_t)base * 64 + idx];
    if (tid < 8) {
        int b = base >> 8;                  // 16 consecutive windows share batch
        ffs[tid] = fmaxf(frag[b] * fw[tid] + fb[tid], 0.f);
    }
    __syncthreads();

    // --- phase 1: projection, stored transposed [k][m] ---
    {
        int j = tid & 63, w0 = tid >> 6;
        float fsum = 0.f;
        #pragma unroll
        for (int k = 0; k < 8; k++) fsum += ffs[k] * prws[(64 + k) * 64 + j];
        float bias = prb[j] + fsum;
        #pragma unroll
        for (int w = 0; w < 4; w++) {
            int wl = w0 * 4 + w;
            float acc = bias;
            #pragma unroll
            for (int k = 0; k < 64; k++) acc += encs[wl * 64 + k] * prws[k * 64 + j];
            featsT[j * 16 + wl] = fmaxf(acc, 0.f);
        }
    }
    __syncthreads();

    // --- phase 2: xg GEMM, f32x2 over window pairs ---
    int g = tid;
    int gp = ((g & 63) << 2) | (g >> 6);   // [j*4 + gate]
    float bias = bih[g] + bhh[g];
    ull acc[8];
    {
        ull bp = bc2(bias);
        #pragma unroll
        for (int m = 0; m < 8; m++) acc[m] = bp;
    }
    #pragma unroll 8
    for (int k = 0; k < 64; k++) {
        ull wv = bc2(wihs[k * GATES + g]);
        ulonglong2 f01 = *(const ulonglong2*)(featsT + k * 16);
        ulonglong2 f23 = *(const ulonglong2*)(featsT + k * 16 + 4);
        ulonglong2 f45 = *(const ulonglong2*)(featsT + k * 16 + 8);
        ulonglong2 f67 = *(const ulonglong2*)(featsT + k * 16 + 12);
        acc[0] = fma2(f01.x, wv, acc[0]);
        acc[1] = fma2(f01.y, wv, acc[1]);
        acc[2] = fma2(f23.x, wv, acc[2]);
        acc[3] = fma2(f23.y, wv, acc[3]);
        acc[4] = fma2(f45.x, wv, acc[4]);
        acc[5] = fma2(f45.y, wv, acc[5]);
        acc[6] = fma2(f67.x, wv, acc[6]);
        acc[7] = fma2(f67.y, wv, acc[7]);
    }
    #pragma unroll
    for (int m = 0; m < 8; m++) {
        float a, b2v;
        upk(a, b2v, acc[m]);
        g_xg[(size_t)(base + 2 * m) * GATES + gp]     = a;
        g_xg[(size_t)(base + 2 * m + 1) * GATES + gp] = b2v;
    }
}

// =====================================================================
// Kernel 3: LSTM. thread = (hidden j = tid>>2, gate = tid&3).
// Whh in registers. xg streamed through SMEM via cp.async.bulk double
// buffer (32-step / 32KB chunks) -> per-step input is a conflict-free
// LDS, with a guaranteed 32-step prefetch horizon.
// =====================================================================
#define CHS 32                      // steps per chunk
#define CHB (CHS * GATES * 4)       // bytes per chunk = 32768
#define NCH (TT / CHS)              // 8 chunks

__device__ __forceinline__ void lstm_step(
    const float* __restrict__ hsrc, float* __restrict__ hdst,
    const ull* wp, const float* __restrict__ xrow, int tid,
    bool isg, bool lead, int j, float& creg, float& hlast,
    float* __restrict__ lo, int t)
{
    float xcur = xrow[tid];                 // LDS, issued early
    ull a0 = 0, a1 = 0, a2 = 0, a3 = 0;
    #pragma unroll
    for (int m = 0; m < 32; m += 4) {
        ulonglong2 hp0 = *(const ulonglong2*)(hsrc + 2 * m);
        ulonglong2 hp1 = *(const ulonglong2*)(hsrc + 2 * m + 4);
        a0 = fma2(hp0.x, wp[m],     a0);
        a1 = fma2(hp0.y, wp[m + 1], a1);
        a2 = fma2(hp1.x, wp[m + 2], a2);
        a3 = fma2(hp1.y, wp[m + 3], a3);
    }
    a0 = add2(a0, a1);
    a2 = add2(a2, a3);
    a0 = add2(a0, a2);
    float slo, shi;
    upk(slo, shi, a0);
    float v = slo + shi + xcur;

    float scale = isg ? (2.f * NLOG2E) : NLOG2E;
    float r = rcpa(1.f + ex2a(v * scale));
    float act = isg ? (2.f * r - 1.f) : r;

    float af = __shfl_down_sync(0xffffffffu, act, 1);
    float ag = __shfl_down_sync(0xffffffffu, act, 2);
    float ao = __shfl_down_sync(0xffffffffu, act, 3);

    if (lead) {
        float c = af * creg + act * ag;       // act = i_act for leader
        creg = c;
        float h = ao * tanha(c);
        hlast = h;
        hdst[j] = h;
        lo[t * PROJ + j] = h;
    }
    __syncthreads();
}

__global__ __launch_bounds__(256) void lstm_kernel(
    const float* __restrict__ Whh, float* __restrict__ outHT,
    float* __restrict__ outCT)
{
    extern __shared__ __align__(16) float xdyn[];     // 2 * 8192 floats
    __shared__ __align__(16) float hsA[64];
    __shared__ __align__(16) float hsB[64];
    __shared__ __align__(8) ull mbarA, mbarB;

    float* xbuf0 = xdyn;
    float* xbuf1 = xdyn + CHS * GATES;

    int tid = threadIdx.x;
    int b = blockIdx.x;
    int gate = tid & 3;
    int j = tid >> 2;
    bool isg = (gate == 2);
    bool lead = (gate == 0);

    ull wp[32];
    const float4* wr = (const float4*)(Whh + (size_t)(gate * 64 + j) * 64);
    #pragma unroll
    for (int m = 0; m < 16; m++) {
        float4 v = wr[m];
        wp[2 * m]     = pk2(v.x, v.y);
        wp[2 * m + 1] = pk2(v.z, v.w);
    }
    unsigned mb0 = smem_u32(&mbarA);
    unsigned mb1 = smem_u32(&mbarB);
    if (tid == 0) {
        mbar_init(mb0, 1);
        mbar_init(mb1, 1);
    }
    if (tid < 64) { hsA[tid] = 0.f; }
    float creg = 0.f, hlast = 0.f;
    __syncthreads();

    const float* xg = g_xg + (size_t)b * TT * GATES;
    float* lo = g_lstm + (size_t)b * TT * PROJ;

    // prologue: issue chunks 0 and 1
    if (tid == 0) {
        mbar_expect(mb0, CHB);
        bulk_g2s(smem_u32(xbuf0), xg, CHB, mb0);
        mbar_expect(mb1, CHB);
        bulk_g2s(smem_u32(xbuf1), xg + CHS * GATES, CHB, mb1);
    }

    for (int c = 0; c < NCH; c++) {
        float* xb = (c & 1) ? xbuf1 : xbuf0;
        unsigned mb = (c & 1) ? mb1 : mb0;
        mbar_wait(mb, (c >> 1) & 1);        // parity: each buffer completes every 2 chunks

        int t0 = c * CHS;
        for (int s = 0; s < CHS; s += 2) {
            lstm_step(hsA, hsB, wp, xb + s * GATES, tid, isg, lead, j,
                      creg, hlast, lo, t0 + s);
            lstm_step(hsB, hsA, wp, xb + (s + 1) * GATES, tid, isg, lead, j,
                      creg, hlast, lo, t0 + s + 1);
        }
        // after the last step's barrier, everyone is done reading chunk c:
        // safe to refill this buffer with chunk c+2.
        if (tid == 0 && c + 2 < NCH) {
            mbar_expect(mb, CHB);
            bulk_g2s(smem_u32(xb), xg + (size_t)(c + 2) * CHS * GATES, CHB, mb);
        }
    }
    if (lead) {
        outHT[b * 64 + j] = hlast;
        outCT[b * 64 + j] = creg;
    }
}

// =====================================================================
// Kernel 4: head  out = sigmoid(lstm_out @ hw^T + hb)
// =====================================================================
__global__ __launch_bounds__(256) void head_kernel(
    const float* __restrict__ hw, const float* __restrict__ hb,
    float* __restrict__ out)
{
    __shared__ float tile[64][65];
    __shared__ float hws[4][64];

    int tid = threadIdx.x;
    int base = blockIdx.x * 64;
    for (int idx = tid; idx < 64 * 64; idx += 256)
        tile[idx >> 6][idx & 63] = g_lstm[(size_t)base * 64 + idx];
    hws[tid >> 6][tid & 63] = hw[tid];
    __syncthreads();

    int wl = tid >> 2, jj = tid & 3;
    float acc = hb[jj];
    #pragma unroll 8
    for (int k = 0; k < 64; k++) acc += tile[wl][k] * hws[jj][k];
    out[(size_t)(base + wl) * 4 + jj] = sigm(acc);
}

// =====================================================================
extern "C" void kernel_launch(void* const* d_in, const int* in_sizes, int n_in,
                              void* d_out, int out_size)
{
    const float* pressure = (const float*)d_in[0];
    const float* torque   = (const float*)d_in[1];
    const float* frag     = (const float*)d_in[2];
    const float* pw1 = (const float*)d_in[3];
    const float* pb1 = (const float*)d_in[4];
    const float* pw2 = (const float*)d_in[5];
    const float* pb2 = (const float*)d_in[6];
    const float* tw1 = (const float*)d_in[7];
    const float* tb1 = (const float*)d_in[8];
    const float* tw2 = (const float*)d_in[9];
    const float* tb2 = (const float*)d_in[10];
    const float* fw  = (const float*)d_in[11];
    const float* fb  = (const float*)d_in[12];
    const float* prw = (const float*)d_in[13];
    const float* prb = (const float*)d_in[14];
    const float* Wih = (const float*)d_in[15];
    const float* Whh = (const float*)d_in[16];
    const float* bih = (const float*)d_in[17];
    const float* bhh = (const float*)d_in[18];
    const float* hw  = (const float*)d_in[19];
    const float* hb  = (const float*)d_in[20];

    float* out   = (float*)d_out;
    float* outHT = out + BB * TT * 4;            // 65536
    float* outCT = outHT + BB * PROJ;            // +4096

    const int projxg_smem = (16384 + 4608 + 1024 + 1024 + 8) * 4;
    cudaFuncSetAttribute(projxg_kernel, cudaFuncAttributeMaxDynamicSharedMemorySize,
                         projxg_smem);
    const int lstm_smem = 2 * CHS * GATES * 4;   // 65536
    cudaFuncSetAttribute(lstm_kernel, cudaFuncAttributeMaxDynamicSharedMemorySize,
                         lstm_smem);
    cudaFuncSetAttribute(enc_kernel, cudaFuncAttributePreferredSharedMemoryCarveout,
                         cudaSharedmemCarveoutMaxShared);

    enc_kernel<<<BT / 4, 128>>>(pressure, torque, pw1, pb1, pw2, pb2,
                                tw1, tb1, tw2, tb2);
    projxg_kernel<<<BT / 16, 256, projxg_smem>>>(frag, fw, fb, prw, prb,
                                                 Wih, bih, bhh);
    lstm_kernel<<<BB, 256, lstm_smem>>>(Whh, outHT, outCT);
    head_kernel<<<BT / 64, 256>>>(hw, hb, out);
}

// round 8
// speedup vs baseline: 1.7354x; 1.1509x over previous
#include <cuda_runtime.h>
#include <cstdint>

// ---------------- problem constants ----------------
#define BB 64
#define TT 256
#define BT (BB*TT)          // 16384 windows
#define WW 20
#define NP 6
#define NT 12
#define CH 32
#define FRAG 8
#define PROJ 64
#define GATES 256           // 4*PROJ

typedef unsigned long long ull;

// ---------------- scratch (static device memory; no allocs allowed) -------
__device__ float g_enc[BT * 64];      // [win][0:32]=pf, [32:64]=tf
__device__ float g_xg[BT * GATES];    // PERMUTED: [win][j*4+gate]
__device__ float g_lstm[BT * PROJ];

// ---------------- MUFU-only activations ----------------
__device__ __forceinline__ float ex2a(float x) {
    float y; asm("ex2.approx.ftz.f32 %0, %1;" : "=f"(y) : "f"(x)); return y;
}
__device__ __forceinline__ float rcpa(float x) {
    float y; asm("rcp.approx.ftz.f32 %0, %1;" : "=f"(y) : "f"(x)); return y;
}
#define NLOG2E -1.4426950408889634f
__device__ __forceinline__ float sigm(float x) {       // 1/(1+e^-x)
    return rcpa(1.f + ex2a(x * NLOG2E));
}
__device__ __forceinline__ float tanha(float x) {      // 2*sig(2x)-1
    return 2.f * rcpa(1.f + ex2a(x * (2.f * NLOG2E))) - 1.f;
}

// ---------------- packed f32x2 helpers (sm_103a) ----------------
__device__ __forceinline__ ull pk2(float a, float b) {
    ull d;
    asm("mov.b64 %0, {%1, %2};" : "=l"(d)
        : "r"(__float_as_uint(a)), "r"(__float_as_uint(b)));
    return d;
}
__device__ __forceinline__ ull bc2(float a) { return pk2(a, a); }
__device__ __forceinline__ void upk(float& a, float& b, ull p) {
    unsigned ua, ub;
    asm("mov.b64 {%0, %1}, %2;" : "=r"(ua), "=r"(ub) : "l"(p));
    a = __uint_as_float(ua); b = __uint_as_float(ub);
}
__device__ __forceinline__ ull fma2(ull a, ull b, ull c) {
    ull d;
    asm("fma.rn.f32x2 %0, %1, %2, %3;" : "=l"(d) : "l"(a), "l"(b), "l"(c));
    return d;
}
__device__ __forceinline__ ull add2(ull a, ull b) {
    ull d;
    asm("add.rn.f32x2 %0, %1, %2;" : "=l"(d) : "l"(a), "l"(b));
    return d;
}

// ---------------- mbarrier / bulk-async helpers ----------------
__device__ __forceinline__ unsigned smem_u32(const void* p) {
    return (unsigned)__cvta_generic_to_shared(p);
}
__device__ __forceinline__ void mbar_init(unsigned a, unsigned cnt) {
    asm volatile("mbarrier.init.shared.b64 [%0], %1;" :: "r"(a), "r"(cnt) : "memory");
}
__device__ __forceinline__ void mbar_expect(unsigned a, unsigned bytes) {
    asm volatile("mbarrier.arrive.expect_tx.shared.b64 _, [%0], %1;"
        :: "r"(a), "r"(bytes) : "memory");
}
__device__ __forceinline__ void bulk_g2s(unsigned dst, const void* src,
                                         unsigned bytes, unsigned mbar) {
    asm volatile(
        "cp.async.bulk.shared::cluster.global.mbarrier::complete_tx::bytes "
        "[%0], [%1], %2, [%3];"
        :: "r"(dst), "l"(src), "r"(bytes), "r"(mbar) : "memory");
}
__device__ __forceinline__ void mbar_wait(unsigned a, unsigned parity) {
    asm volatile(
        "{\n\t.reg .pred P;\n"
        "WL_%=:\n\t"
        "mbarrier.try_wait.parity.acquire.cta.shared::cta.b64 P, [%0], %1;\n\t"
        "@!P bra WL_%=;\n\t}"
        :: "r"(a), "r"(parity) : "memory");
}

// =====================================================================
// Encoder building blocks
// =====================================================================
template<int CIN, int NLD>
__device__ __forceinline__ void load_x_regs(float* r, const float* __restrict__ g,
                                            int lane) {
    #pragma unroll
    for (int k = 0; k < NLD; k++) {
        int idx = lane + 32 * k;
        r[k] = (idx < CIN * 20) ? g[idx] : 0.f;
    }
}
template<int CIN, int NLD>
__device__ __forceinline__ void store_x_smem(float* xs, const float* r, int lane) {
    #pragma unroll
    for (int k = 0; k < NLD; k++) {
        int idx = lane + 32 * k;
        if (idx < CIN * 20) xs[(idx % CIN) * 24 + idx / CIN] = r[k];
    }
}

// conv-relu-conv-relu-pool; xs ([cin][24]) must be pre-filled.
template<int CIN>
__device__ __forceinline__ float encode_one(
    const float* __restrict__ w1s, const float* __restrict__ w2s,
    float b1, float b2, const float* xs, float* h1s, int lane)
{
    // ---- conv1: CIN -> 32, L 20 -> 18 ----
    ull accE[9], accO[10];
    {
        ull bp = bc2(b1);
        #pragma unroll
        for (int m = 0; m < 9; m++)  accE[m] = bp;
        #pragma unroll
        for (int m = 0; m < 10; m++) accO[m] = 0ull;
    }
    #pragma unroll
    for (int i = 0; i < CIN; i++) {
        const float* xr = xs + i * 24;
        ulonglong2 q0 = *(const ulonglong2*)(xr);
        ulonglong2 q1 = *(const ulonglong2*)(xr + 4);
        ulonglong2 q2 = *(const ulonglong2*)(xr + 8);
        ulonglong2 q3 = *(const ulonglong2*)(xr + 12);
        ulonglong2 q4 = *(const ulonglong2*)(xr + 16);
        ull x2[10] = {q0.x, q0.y, q1.x, q1.y, q2.x, q2.y, q3.x, q3.y, q4.x, q4.y};
        ull w0 = bc2(w1s[(i * 3 + 0) * 32 + lane]);
        ull w1 = bc2(w1s[(i * 3 + 1) * 32 + lane]);
        ull w2 = bc2(w1s[(i * 3 + 2) * 32 + lane]);
        #pragma unroll
        for (int m = 0; m < 9; m++)  accE[m] = fma2(x2[m], w0, accE[m]);
        #pragma unroll
        for (int m = 0; m < 10; m++) accO[m] = fma2(x2[m], w1, accO[m]);
        #pragma unroll
        for (int m = 1; m < 10; m++) accE[m - 1] = fma2(x2[m], w2, accE[m - 1]);
    }
    {
        float ol0, oh0;
        upk(ol0, oh0, accO[0]);
        #pragma unroll
        for (int m = 0; m < 9; m++) {
            float el, eh, ol1, oh1;
            upk(el, eh, accE[m]);
            upk(ol1, oh1, accO[m + 1]);
            float h0 = fmaxf(el + oh0, 0.f);
            float h1 = fmaxf(eh + ol1, 0.f);
            *(ull*)(h1s + lane * 24 + 2 * m) = pk2(h0, h1);
            oh0 = oh1;
        }
    }
    __syncwarp();

    // ---- conv2: 32 -> 32, L 18 -> 16, then avg pool ----
    ull aE[8], aO[9];
    {
        ull bp = bc2(b2);
        #pragma unroll
        for (int m = 0; m < 8; m++) aE[m] = bp;
        #pragma unroll
        for (int m = 0; m < 9; m++) aO[m] = 0ull;
    }
    #pragma unroll 8
    for (int ci = 0; ci < 32; ci++) {
        const float* hr = h1s + ci * 24;
        ulonglong2 q0 = *(const ulonglong2*)(hr);
        ulonglong2 q1 = *(const ulonglong2*)(hr + 4);
        ulonglong2 q2 = *(const ulonglong2*)(hr + 8);
        ulonglong2 q3 = *(const ulonglong2*)(hr + 12);
        ull q4 = *(const ull*)(hr + 16);
        ull x2[9] = {q0.x, q0.y, q1.x, q1.y, q2.x, q2.y, q3.x, q3.y, q4};
        ull w0 = bc2(w2s[(ci * 3 + 0) * 32 + lane]);
        ull w1 = bc2(w2s[(ci * 3 + 1) * 32 + lane]);
        ull w2 = bc2(w2s[(ci * 3 + 2) * 32 + lane]);
        #pragma unroll
        for (int m = 0; m < 8; m++) aE[m] = fma2(x2[m], w0, aE[m]);
        #pragma unroll
        for (int m = 0; m < 9; m++) aO[m] = fma2(x2[m], w1, aO[m]);
        #pragma unroll
        for (int m = 1; m < 9; m++) aE[m - 1] = fma2(x2[m], w2, aE[m - 1]);
    }
    float s = 0.f;
    {
        float ol0, oh0;
        upk(ol0, oh0, aO[0]);
        #pragma unroll
        for (int m = 0; m < 8; m++) {
            float el, eh, ol1, oh1;
            upk(el, eh, aE[m]);
            upk(ol1, oh1, aO[m + 1]);
            s += fmaxf(el + oh0, 0.f);
            s += fmaxf(eh + ol1, 0.f);
            oh0 = oh1;
        }
    }
    __syncwarp();
    return s * (1.f / 16.f);
}

// =====================================================================
// Kernel 1: persistent conv encoders. 592 blocks (4/SM), warp grid-
// strides over ~7 windows; next window's inputs prefetched to registers
// while the current window computes (hides DRAM latency); weight
// staging amortized across all windows of the block.
// =====================================================================
#define ENC_BLOCKS 592

__global__ __launch_bounds__(128, 4) void enc_kernel(
    const float* __restrict__ pressure, const float* __restrict__ torque,
    const float* __restrict__ pw1, const float* __restrict__ pb1,
    const float* __restrict__ pw2, const float* __restrict__ pb2,
    const float* __restrict__ tw1, const float* __restrict__ tb1,
    const float* __restrict__ tw2, const float* __restrict__ tb2)
{
    __shared__ __align__(16) float pw1s[18 * 32];
    __shared__ __align__(16) float pw2s[96 * 32];
    __shared__ __align__(16) float tw1s[36 * 32];
    __shared__ __align__(16) float tw2s[96 * 32];
    __shared__ __align__(16) float xs[4][12 * 24];
    __shared__ __align__(16) float h1s[4][32 * 24];

    int tid = threadIdx.x;
    for (int idx = tid; idx < 32 * 18; idx += 128) {
        int c = idx / 18, r = idx % 18;
        pw1s[r * 32 + c] = pw1[idx];
    }
    for (int idx = tid; idx < 32 * 96; idx += 128) {
        int c = idx / 96, r = idx % 96;
        pw2s[r * 32 + c] = pw2[idx];
        tw2s[r * 32 + c] = tw2[idx];
    }
    for (int idx = tid; idx < 32 * 36; idx += 128) {
        int c = idx / 36, r = idx % 36;
        tw1s[r * 32 + c] = tw1[idx];
    }
    __syncthreads();

    int w = tid >> 5, lane = tid & 31;
    const int stride = ENC_BLOCKS * 4;
    float pb1l = pb1[lane], pb2l = pb2[lane];
    float tb1l = tb1[lane], tb2l = tb2[lane];

    int win = blockIdx.x * 4 + w;
    float px[4], tx[8];
    load_x_regs<NP, 4>(px, pressure + (size_t)win * (WW * NP), lane);
    load_x_regs<NT, 8>(tx, torque + (size_t)win * (WW * NT), lane);

    while (win < BT) {
        int wnext = win + stride;
        bool more = (wnext < BT);

        // pressure
        store_x_smem<NP, 4>(xs[w], px, lane);
        __syncwarp();
        if (more) load_x_regs<NP, 4>(px, pressure + (size_t)wnext * (WW * NP), lane);
        float pf = encode_one<NP>(pw1s, pw2s, pb1l, pb2l, xs[w], h1s[w], lane);
        g_enc[(size_t)win * 64 + lane] = pf;
        __syncwarp();

        // torque
        store_x_smem<NT, 8>(xs[w], tx, lane);
        __syncwarp();
        if (more) load_x_regs<NT, 8>(tx, torque + (size_t)wnext * (WW * NT), lane);
        float tf = encode_one<NT>(tw1s, tw2s, tb1l, tb2l, xs[w], h1s[w], lane);
        g_enc[(size_t)win * 64 + 32 + lane] = tf;
        __syncwarp();

        win = wnext;
    }
}

// =====================================================================
// Kernel 2: FUSED projection + xg. 16 windows per block.
// =====================================================================
__global__ __launch_bounds__(256) void projxg_kernel(
    const float* __restrict__ frag, const float* __restrict__ fw,
    const float* __restrict__ fb,   const float* __restrict__ prw,
    const float* __restrict__ prb,  const float* __restrict__ Wih,
    const float* __restrict__ bih,  const float* __restrict__ bhh)
{
    extern __shared__ __align__(16) float sm[];
    float* wihs   = sm;                     // 64*256 = 16384  [k][g]
    float* prws   = sm + 16384;             // 72*64  = 4608   [k][j]
    float* encs   = sm + 16384 + 4608;      // 16*64  = 1024
    float* featsT = encs + 1024;            // 64*16  = 1024   [k][m]
    float* ffs    = featsT + 1024;          // 8

    int tid = threadIdx.x;
    int base = blockIdx.x * 16;

    for (int idx = tid; idx < GATES * 64; idx += 256) {
        int g = idx / 64, k = idx % 64;
        wihs[k * GATES + g] = Wih[idx];
    }
    for (int idx = tid; idx < 64 * 72; idx += 256) {
        int j = idx / 72, k = idx % 72;
        prws[k * 64 + j] = prw[idx];
    }
    for (int idx = tid; idx < 16 * 64; idx += 256)
        encs[idx] = g_enc[(size_t)base * 64 + idx];
    if (tid < 8) {
        int b = base >> 8;                  // 16 consecutive windows share batch
        ffs[tid] = fmaxf(frag[b] * fw[tid] + fb[tid], 0.f);
    }
    __syncthreads();

    // --- phase 1: projection, stored transposed [k][m] ---
    {
        int j = tid & 63, w0 = tid >> 6;
        float fsum = 0.f;
        #pragma unroll
        for (int k = 0; k < 8; k++) fsum += ffs[k] * prws[(64 + k) * 64 + j];
        float bias = prb[j] + fsum;
        #pragma unroll
        for (int w = 0; w < 4; w++) {
            int wl = w0 * 4 + w;
            float acc = bias;
            #pragma unroll
            for (int k = 0; k < 64; k++) acc += encs[wl * 64 + k] * prws[k * 64 + j];
            featsT[j * 16 + wl] = fmaxf(acc, 0.f);
        }
    }
    __syncthreads();

    // --- phase 2: xg GEMM, f32x2 over window pairs ---
    int g = tid;
    int gp = ((g & 63) << 2) | (g >> 6);   // [j*4 + gate]
    float bias = bih[g] + bhh[g];
    ull acc[8];
    {
        ull bp = bc2(bias);
        #pragma unroll
        for (int m = 0; m < 8; m++) acc[m] = bp;
    }
    #pragma unroll 8
    for (int k = 0; k < 64; k++) {
        ull wv = bc2(wihs[k * GATES + g]);
        ulonglong2 f01 = *(const ulonglong2*)(featsT + k * 16);
        ulonglong2 f23 = *(const ulonglong2*)(featsT + k * 16 + 4);
        ulonglong2 f45 = *(const ulonglong2*)(featsT + k * 16 + 8);
        ulonglong2 f67 = *(const ulonglong2*)(featsT + k * 16 + 12);
        acc[0] = fma2(f01.x, wv, acc[0]);
        acc[1] = fma2(f01.y, wv, acc[1]);
        acc[2] = fma2(f23.x, wv, acc[2]);
        acc[3] = fma2(f23.y, wv, acc[3]);
        acc[4] = fma2(f45.x, wv, acc[4]);
        acc[5] = fma2(f45.y, wv, acc[5]);
        acc[6] = fma2(f67.x, wv, acc[6]);
        acc[7] = fma2(f67.y, wv, acc[7]);
    }
    #pragma unroll
    for (int m = 0; m < 8; m++) {
        float a, b2v;
        upk(a, b2v, acc[m]);
        g_xg[(size_t)(base + 2 * m) * GATES + gp]     = a;
        g_xg[(size_t)(base + 2 * m + 1) * GATES + gp] = b2v;
    }
}

// =====================================================================
// Kernel 3: LSTM, 512 threads split-K.
// thread = (j = tid>>3, gate = (tid>>1)&3, half = tid&1).
// Each thread: 32-wide half-dot (16 fma2, weights in 32 regs), combine
// via shfl_xor(1); leader (tid%8==0) gathers acts via shfl_down 2/4/6.
// xg streamed through SMEM via cp.async.bulk double buffer.
// =====================================================================
#define CHS 32                      // steps per chunk
#define CHB (CHS * GATES * 4)       // bytes per chunk = 32768
#define NCH (TT / CHS)              // 8 chunks

__device__ __forceinline__ void lstm_step(
    const float* __restrict__ hsrc, float* __restrict__ hdst,
    const ull* wp, const float* __restrict__ xrow, int tid,
    int half, bool isg, bool lead, int j, float& creg, float& hlast,
    float* __restrict__ lo, int t)
{
    float xcur = xrow[tid >> 1];            // 2-way broadcast LDS
    const float* hb = hsrc + half * 32;
    ull a0 = 0, a1 = 0, a2 = 0, a3 = 0;
    #pragma unroll
    for (int m = 0; m < 16; m += 4) {
        ulonglong2 hp0 = *(const ulonglong2*)(hb + 2 * m);
        ulonglong2 hp1 = *(const ulonglong2*)(hb + 2 * m + 4);
        a0 = fma2(hp0.x, wp[m],     a0);
        a1 = fma2(hp0.y, wp[m + 1], a1);
        a2 = fma2(hp1.x, wp[m + 2], a2);
        a3 = fma2(hp1.y, wp[m + 3], a3);
    }
    a0 = add2(a0, a1);
    a2 = add2(a2, a3);
    a0 = add2(a0, a2);
    float slo, shi;
    upk(slo, shi, a0);
    float vh = slo + shi;
    float v = vh + __shfl_xor_sync(0xffffffffu, vh, 1) + xcur;

    float scale = isg ? (2.f * NLOG2E) : NLOG2E;
    float r = rcpa(1.f + ex2a(v * scale));
    float act = isg ? (2.f * r - 1.f) : r;

    float af = __shfl_down_sync(0xffffffffu, act, 2);
    float ag = __shfl_down_sync(0xffffffffu, act, 4);
    float ao = __shfl_down_sync(0xffffffffu, act, 6);

    if (lead) {
        float c = af * creg + act * ag;       // act = i_act for leader
        creg = c;
        float h = ao * tanha(c);
        hlast = h;
        hdst[j] = h;
        lo[t * PROJ + j] = h;
    }
    __syncthreads();
}

__global__ __launch_bounds__(512) void lstm_kernel(
    const float* __restrict__ Whh, float* __restrict__ outHT,
    float* __restrict__ outCT)
{
    extern __shared__ __align__(16) float xdyn[];     // 2 * 8192 floats
    __shared__ __align__(16) float hsA[64];
    __shared__ __align__(16) float hsB[64];
    __shared__ __align__(8) ull mbarA, mbarB;

    float* xbuf0 = xdyn;
    float* xbuf1 = xdyn + CHS * GATES;

    int tid = threadIdx.x;
    int b = blockIdx.x;
    int half = tid & 1;
    int gate = (tid >> 1) & 3;
    int j = tid >> 3;
    bool isg = (gate == 2);
    bool lead = ((tid & 7) == 0);

    // Whh[gate*64+j][half*32 .. +32] into 16 packed regs
    ull wp[16];
    const float4* wr = (const float4*)(Whh + (size_t)(gate * 64 + j) * 64 + half * 32);
    #pragma unroll
    for (int m = 0; m < 8; m++) {
        float4 v = wr[m];
        wp[2 * m]     = pk2(v.x, v.y);
        wp[2 * m + 1] = pk2(v.z, v.w);
    }
    unsigned mb0 = smem_u32(&mbarA);
    unsigned mb1 = smem_u32(&mbarB);
    if (tid == 0) {
        mbar_init(mb0, 1);
        mbar_init(mb1, 1);
    }
    if (tid < 64) { hsA[tid] = 0.f; }
    float creg = 0.f, hlast = 0.f;
    __syncthreads();

    const float* xg = g_xg + (size_t)b * TT * GATES;
    float* lo = g_lstm + (size_t)b * TT * PROJ;

    // prologue: issue chunks 0 and 1
    if (tid == 0) {
        mbar_expect(mb0, CHB);
        bulk_g2s(smem_u32(xbuf0), xg, CHB, mb0);
        mbar_expect(mb1, CHB);
        bulk_g2s(smem_u32(xbuf1), xg + CHS * GATES, CHB, mb1);
    }

    for (int c = 0; c < NCH; c++) {
        float* xb = (c & 1) ? xbuf1 : xbuf0;
        unsigned mb = (c & 1) ? mb1 : mb0;
        mbar_wait(mb, (c >> 1) & 1);

        int t0 = c * CHS;
        for (int s = 0; s < CHS; s += 2) {
            lstm_step(hsA, hsB, wp, xb + s * GATES, tid, half, isg, lead, j,
                      creg, hlast, lo, t0 + s);
            lstm_step(hsB, hsA, wp, xb + (s + 1) * GATES, tid, half, isg, lead, j,
                      creg, hlast, lo, t0 + s + 1);
        }
        if (tid == 0 && c + 2 < NCH) {
            mbar_expect(mb, CHB);
            bulk_g2s(smem_u32(xb), xg + (size_t)(c + 2) * CHS * GATES, CHB, mb);
        }
    }
    if (lead) {
        outHT[b * 64 + j] = hlast;
        outCT[b * 64 + j] = creg;
    }
}

// =====================================================================
// Kernel 4: head  out = sigmoid(lstm_out @ hw^T + hb)
// =====================================================================
__global__ __launch_bounds__(256) void head_kernel(
    const float* __restrict__ hw, const float* __restrict__ hb,
    float* __restrict__ out)
{
    __shared__ float tile[64][65];
    __shared__ float hws[4][64];

    int tid = threadIdx.x;
    int base = blockIdx.x * 64;
    for (int idx = tid; idx < 64 * 64; idx += 256)
        tile[idx >> 6][idx & 63] = g_lstm[(size_t)base * 64 + idx];
    hws[tid >> 6][tid & 63] = hw[tid];
    __syncthreads();

    int wl = tid >> 2, jj = tid & 3;
    float acc = hb[jj];
    #pragma unroll 8
    for (int k = 0; k < 64; k++) acc += tile[wl][k] * hws[jj][k];
    out[(size_t)(base + wl) * 4 + jj] = sigm(acc);
}

// =====================================================================
extern "C" void kernel_launch(void* const* d_in, const int* in_sizes, int n_in,
                              void* d_out, int out_size)
{
    const float* pressure = (const float*)d_in[0];
    const float* torque   = (const float*)d_in[1];
    const float* frag     = (const float*)d_in[2];
    const float* pw1 = (const float*)d_in[3];
    const float* pb1 = (const float*)d_in[4];
    const float* pw2 = (const float*)d_in[5];
    const float* pb2 = (const float*)d_in[6];
    const float* tw1 = (const float*)d_in[7];
    const float* tb1 = (const float*)d_in[8];
    const float* tw2 = (const float*)d_in[9];
    const float* tb2 = (const float*)d_in[10];
    const float* fw  = (const float*)d_in[11];
    const float* fb  = (const float*)d_in[12];
    const float* prw = (const float*)d_in[13];
    const float* prb = (const float*)d_in[14];
    const float* Wih = (const float*)d_in[15];
    const float* Whh = (const float*)d_in[16];
    const float* bih = (const float*)d_in[17];
    const float* bhh = (const float*)d_in[18];
    const float* hw  = (const float*)d_in[19];
    const float* hb  = (const float*)d_in[20];

    float* out   = (float*)d_out;
    float* outHT = out + BB * TT * 4;            // 65536
    float* outCT = outHT + BB * PROJ;            // +4096

    const int projxg_smem = (16384 + 4608 + 1024 + 1024 + 8) * 4;
    cudaFuncSetAttribute(projxg_kernel, cudaFuncAttributeMaxDynamicSharedMemorySize,
                         projxg_smem);
    const int lstm_smem = 2 * CHS * GATES * 4;   // 65536
    cudaFuncSetAttribute(lstm_kernel, cudaFuncAttributeMaxDynamicSharedMemorySize,
                         lstm_smem);
    cudaFuncSetAttribute(enc_kernel, cudaFuncAttributePreferredSharedMemoryCarveout,
                         cudaSharedmemCarveoutMaxShared);

    enc_kernel<<<ENC_BLOCKS, 128>>>(pressure, torque, pw1, pb1, pw2, pb2,
                                    tw1, tb1, tw2, tb2);
    projxg_kernel<<<BT / 16, 256, projxg_smem>>>(frag, fw, fb, prw, prb,
                                                 Wih, bih, bhh);
    lstm_kernel<<<BB, 512, lstm_smem>>>(Whh, outHT, outCT);
    head_kernel<<<BT / 64, 256>>>(hw, hb, out);
}